// round 13
// baseline (speedup 1.0000x reference)
#include <cuda_runtime.h>
#include <cuda_bf16.h>
#include <cuda_fp16.h>
#include <math.h>
#include <stdint.h>

// ---------------------------------------------------------------------------
// EfficientTransformerEncoder: B=32, D=256 -> L=1024, NH=8, NL=3, DFF=1024,
// WIN=64. bf16 mma.sync GEMMs (wide 128x256 tiles) + fp16 TC attention.
// ---------------------------------------------------------------------------

#define T_TOK   32768
#define DMODEL  256
#define DQKV    768
#define DFFN    1024

__device__ float          g_x  [(size_t)T_TOK * DMODEL];
__device__ __nv_bfloat16  g_xb [(size_t)T_TOK * DMODEL];
__device__ __half         g_qkv[(size_t)T_TOK * DQKV];
__device__ __nv_bfloat16  g_att[(size_t)T_TOK * DMODEL];
__device__ __nv_bfloat16  g_h  [(size_t)T_TOK * DFFN];

#define WT_INW 0
#define WT_OW  (WT_INW + 3 * DQKV * DMODEL)
#define WT_W1  (WT_OW  + 3 * DMODEL * DMODEL)
#define WT_W2  (WT_W1  + 3 * DFFN * DMODEL)
#define WT_TOT (WT_W2  + 3 * DMODEL * DFFN)
__device__ __nv_bfloat16 g_wb[WT_TOT];

#define CV0 0
#define CV1 (WT_OW  / 4)
#define CV2 (WT_W1  / 4)
#define CV3 (WT_W2  / 4)
#define CV4 (WT_TOT / 4)

// ---------------------------------------------------------------------------
__global__ void cvt_all(const float* __restrict__ s0, const float* __restrict__ s1,
                        const float* __restrict__ s2, const float* __restrict__ s3,
                        __nv_bfloat16* __restrict__ dst) {
    int i = blockIdx.x * blockDim.x + threadIdx.x;
    if (i >= CV4) return;
    const float* src;
    int off;
    if (i < CV1)      { src = s0; off = i - CV0; }
    else if (i < CV2) { src = s1; off = i - CV1; }
    else if (i < CV3) { src = s2; off = i - CV2; }
    else              { src = s3; off = i - CV3; }
    float4 v = ((const float4*)src)[off];
    __nv_bfloat162 lo = {__float2bfloat16_rn(v.x), __float2bfloat16_rn(v.y)};
    __nv_bfloat162 hi = {__float2bfloat16_rn(v.z), __float2bfloat16_rn(v.w)};
    ((__nv_bfloat162*)dst)[i * 2]     = lo;
    ((__nv_bfloat162*)dst)[i * 2 + 1] = hi;
}

// ---------------------------------------------------------------------------
__device__ __forceinline__ float pe_val(int l, int d) {
    int i = d >> 1;
    float freq = expf(-(float)(2 * i) * 0.0359778920439f);
    float ang = (float)l * freq;
    return (d & 1) ? cosf(ang) : sinf(ang);
}

__global__ void embed_kernel(const float* __restrict__ f,
                             float* __restrict__ x, __nv_bfloat16* __restrict__ xb) {
    __shared__ float tile[32][33];
    int b  = blockIdx.z;
    int l0 = blockIdx.x * 32, d0 = blockIdx.y * 32;
    int tx = threadIdx.x, ty = threadIdx.y;
    tile[ty][tx] = f[((size_t)b * DMODEL + d0 + ty) * 1024 + l0 + tx];
    __syncthreads();
    int l = l0 + ty, d = d0 + tx;
    float v = tile[tx][ty] + pe_val(l, d);
    size_t idx = ((size_t)b * 1024 + l) * DMODEL + d;
    x[idx]  = v;
    xb[idx] = __float2bfloat16_rn(v);
}

// ---------------------------------------------------------------------------
__device__ __forceinline__ float gelu_exact(float v) {
    return 0.5f * v * (1.0f + erff(v * 0.7071067811865476f));
}

__device__ __forceinline__ void mma_bf16(float c[4], const uint32_t a[4], const uint32_t b[2]) {
    asm volatile(
        "mma.sync.aligned.m16n8k16.row.col.f32.bf16.bf16.f32 "
        "{%0,%1,%2,%3}, {%4,%5,%6,%7}, {%8,%9}, {%0,%1,%2,%3};\n"
        : "+f"(c[0]), "+f"(c[1]), "+f"(c[2]), "+f"(c[3])
        : "r"(a[0]), "r"(a[1]), "r"(a[2]), "r"(a[3]), "r"(b[0]), "r"(b[1]));
}

__device__ __forceinline__ void mma_fp16(float c[4], const uint32_t a[4], const uint32_t b[2]) {
    asm volatile(
        "mma.sync.aligned.m16n8k16.row.col.f32.f16.f16.f32 "
        "{%0,%1,%2,%3}, {%4,%5,%6,%7}, {%8,%9}, {%0,%1,%2,%3};\n"
        : "+f"(c[0]), "+f"(c[1]), "+f"(c[2]), "+f"(c[3])
        : "r"(a[0]), "r"(a[1]), "r"(a[2]), "r"(a[3]), "r"(b[0]), "r"(b[1]));
}

__device__ __forceinline__ void ldsm4(uint32_t& r0, uint32_t& r1, uint32_t& r2, uint32_t& r3,
                                      uint32_t addr) {
    asm volatile("ldmatrix.sync.aligned.m8n8.x4.shared.b16 {%0,%1,%2,%3}, [%4];"
                 : "=r"(r0), "=r"(r1), "=r"(r2), "=r"(r3) : "r"(addr));
}
__device__ __forceinline__ void ldsm4t(uint32_t& r0, uint32_t& r1, uint32_t& r2, uint32_t& r3,
                                       uint32_t addr) {
    asm volatile("ldmatrix.sync.aligned.m8n8.x4.trans.shared.b16 {%0,%1,%2,%3}, [%4];"
                 : "=r"(r0), "=r"(r1), "=r"(r2), "=r"(r3) : "r"(addr));
}

__device__ __forceinline__ void cpa16(uint32_t dst, const void* src) {
    asm volatile("cp.async.cg.shared.global [%0], [%1], 16;\n" :: "r"(dst), "l"(src));
}
__device__ __forceinline__ void cpa_commit() {
    asm volatile("cp.async.commit_group;\n" ::: "memory");
}
__device__ __forceinline__ void cpa_wait0() {
    asm volatile("cp.async.wait_group 0;\n" ::: "memory");
}

__device__ __forceinline__ uint32_t packh2(float x, float y) {
    __half2 h = __floats2half2_rn(x, y);
    return *reinterpret_cast<uint32_t*>(&h);
}

#define SMH  72
#define ROWB (SMH * 2)

// ---------------------------------------------------------------------------
// Wide bf16 GEMM: block 128(M) x 256(N), k64 tiles, 256 threads (2x4 warps),
// warp tile 64x64. 2-stage cp.async. outmode: 1 -> bf16, 2 -> fp16.
// Requires N % 256 == 0.
// ---------------------------------------------------------------------------
#define WA_B (128 * ROWB)              // 18432
#define WB_B (256 * ROWB)              // 36864
#define WG_SMEM (2 * WA_B + 2 * WB_B)  // 110592

__global__ void __launch_bounds__(256)
gemm_wide(const __nv_bfloat16* __restrict__ A, const __nv_bfloat16* __restrict__ B,
          const float* __restrict__ bias,
          __nv_bfloat16* __restrict__ Cb, __half* __restrict__ Ch,
          int M, int N, int K, int act, int outmode)
{
    extern __shared__ __nv_bfloat16 smem[];
    uint32_t sbase = (uint32_t)__cvta_generic_to_shared(smem);
    uint32_t aBase = sbase;
    uint32_t bBase = sbase + 2 * WA_B;

    int tid  = threadIdx.x;
    int warp = tid >> 5, lane = tid & 31;
    int wm = (warp >> 2) * 64;
    int wn = (warp & 3) * 64;
    int grp = lane >> 2, tig = lane & 3;

    const __nv_bfloat16* Ab = A + (size_t)blockIdx.y * 128 * K;
    const __nv_bfloat16* Bb = B + (size_t)blockIdx.x * 256 * K;

    // A: 1024 chunks (4/thread); B: 2048 chunks (8/thread)
    int aRowc[4], aChoff[4];
#pragma unroll
    for (int i = 0; i < 4; i++) {
        int c = tid + 256 * i;
        aRowc[i]  = c >> 3;
        aChoff[i] = (c & 7) * 8;
    }
    int bRowc[8], bChoff[8];
#pragma unroll
    for (int i = 0; i < 8; i++) {
        int c = tid + 256 * i;
        bRowc[i]  = c >> 3;
        bChoff[i] = (c & 7) * 8;
    }

    int aRow = wm + ((lane >> 3) & 1) * 8 + (lane & 7);
    int aK   = (lane >> 4) * 8;
    int bRow = wn + (lane >> 4) * 8 + (lane & 7);
    int bK   = ((lane >> 3) & 1) * 8;
    uint32_t aAddr = aBase + (uint32_t)aRow * ROWB + (uint32_t)aK * 2;
    uint32_t bAddr = bBase + (uint32_t)bRow * ROWB + (uint32_t)bK * 2;

    float acc[4][8][4];
#pragma unroll
    for (int mi = 0; mi < 4; mi++)
#pragma unroll
        for (int ni = 0; ni < 8; ni++)
#pragma unroll
            for (int r = 0; r < 4; r++) acc[mi][ni][r] = 0.0f;

    int nt = K >> 6;

#define WLOAD_TILE(t)                                                          \
    do {                                                                       \
        uint32_t oa_ = (uint32_t)((t) & 1) * WA_B;                             \
        uint32_t ob_ = (uint32_t)((t) & 1) * WB_B;                             \
        int k0_ = (t) << 6;                                                    \
        _Pragma("unroll")                                                      \
        for (int i_ = 0; i_ < 4; i_++)                                         \
            cpa16(aBase + oa_ + (uint32_t)aRowc[i_] * ROWB + (uint32_t)aChoff[i_] * 2, \
                  Ab + (size_t)aRowc[i_] * K + k0_ + aChoff[i_]);              \
        _Pragma("unroll")                                                      \
        for (int i_ = 0; i_ < 8; i_++)                                         \
            cpa16(bBase + ob_ + (uint32_t)bRowc[i_] * ROWB + (uint32_t)bChoff[i_] * 2, \
                  Bb + (size_t)bRowc[i_] * K + k0_ + bChoff[i_]);              \
        cpa_commit();                                                          \
    } while (0)

    WLOAD_TILE(0);

    for (int j = 0; j < nt; j++) {
        cpa_wait0();
        __syncthreads();
        if (j + 1 < nt) WLOAD_TILE(j + 1);

        uint32_t aOff = (uint32_t)(j & 1) * WA_B;
        uint32_t bOff = (uint32_t)(j & 1) * WB_B;
#pragma unroll
        for (int ks = 0; ks < 4; ks++) {
            uint32_t kb = (uint32_t)(ks * 32);
            uint32_t af[4][4], bf[8][2];
#pragma unroll
            for (int mi = 0; mi < 4; mi++)
                ldsm4(af[mi][0], af[mi][1], af[mi][2], af[mi][3],
                      aAddr + aOff + kb + (uint32_t)(mi * 16) * ROWB);
#pragma unroll
            for (int pi = 0; pi < 4; pi++)
                ldsm4(bf[2 * pi][0], bf[2 * pi][1], bf[2 * pi + 1][0], bf[2 * pi + 1][1],
                      bAddr + bOff + kb + (uint32_t)(pi * 16) * ROWB);
#pragma unroll
            for (int mi = 0; mi < 4; mi++)
#pragma unroll
                for (int ni = 0; ni < 8; ni++)
                    mma_bf16(acc[mi][ni], af[mi], bf[ni]);
        }
    }

#pragma unroll
    for (int mi = 0; mi < 4; mi++) {
        int r0 = blockIdx.y * 128 + wm + mi * 16 + grp;
#pragma unroll
        for (int ni = 0; ni < 8; ni++) {
            int c = blockIdx.x * 256 + wn + ni * 8 + tig * 2;
            float bv0 = __ldg(bias + c), bv1 = __ldg(bias + c + 1);
            float v0 = acc[mi][ni][0] + bv0;
            float v1 = acc[mi][ni][1] + bv1;
            float v2 = acc[mi][ni][2] + bv0;
            float v3 = acc[mi][ni][3] + bv1;
            if (act == 1) {
                v0 = gelu_exact(v0); v1 = gelu_exact(v1);
                v2 = gelu_exact(v2); v3 = gelu_exact(v3);
            }
            if (outmode == 1) {
                __nv_bfloat162 p0 = {__float2bfloat16_rn(v0), __float2bfloat16_rn(v1)};
                __nv_bfloat162 p1 = {__float2bfloat16_rn(v2), __float2bfloat16_rn(v3)};
                *(__nv_bfloat162*)(Cb + (size_t)r0 * N + c) = p0;
                *(__nv_bfloat162*)(Cb + (size_t)(r0 + 8) * N + c) = p1;
            } else {
                uint32_t p0 = packh2(v0, v1), p1 = packh2(v2, v3);
                *(uint32_t*)(Ch + (size_t)r0 * N + c) = p0;
                *(uint32_t*)(Ch + (size_t)(r0 + 8) * N + c) = p1;
            }
        }
    }
}

// ---------------------------------------------------------------------------
// Fused GEMM(N=256) + residual + LayerNorm. Block tile 64x256, 8 warps (1x8).
// ---------------------------------------------------------------------------
#define FA_B  (64 * ROWB)
#define FB_B  (256 * ROWB)
#define FG_SMEM (2 * FA_B + 2 * FB_B)
#define STG_S 264

__global__ void __launch_bounds__(256, 2)
gemm_ln(const __nv_bfloat16* __restrict__ A, const __nv_bfloat16* __restrict__ B,
        const float* __restrict__ bias,
        const float* __restrict__ lns, const float* __restrict__ lnb,
        float* __restrict__ x, __nv_bfloat16* __restrict__ xb, int K)
{
    extern __shared__ __nv_bfloat16 smem[];
    uint32_t sbase = (uint32_t)__cvta_generic_to_shared(smem);
    uint32_t aBase = sbase;
    uint32_t bBase = sbase + 2 * FA_B;

    int tid  = threadIdx.x;
    int warp = tid >> 5, lane = tid & 31;
    int wn = warp * 32;
    int grp = lane >> 2, tig = lane & 3;

    const __nv_bfloat16* Ab = A + (size_t)blockIdx.x * 64 * K;

    int aRowc[2], aChoff[2];
#pragma unroll
    for (int i = 0; i < 2; i++) {
        int c = tid + 256 * i;
        aRowc[i]  = c >> 3;
        aChoff[i] = (c & 7) * 8;
    }
    int bRowc[8], bChoff[8];
#pragma unroll
    for (int i = 0; i < 8; i++) {
        int c = tid + 256 * i;
        bRowc[i]  = c >> 3;
        bChoff[i] = (c & 7) * 8;
    }

    int aRow = ((lane >> 3) & 1) * 8 + (lane & 7);
    int aK   = (lane >> 4) * 8;
    int bRow = wn + (lane >> 4) * 8 + (lane & 7);
    int bK   = ((lane >> 3) & 1) * 8;
    uint32_t aAddr = aBase + (uint32_t)aRow * ROWB + (uint32_t)aK * 2;
    uint32_t bAddr = bBase + (uint32_t)bRow * ROWB + (uint32_t)bK * 2;

    float acc[4][4][4];
#pragma unroll
    for (int mi = 0; mi < 4; mi++)
#pragma unroll
        for (int ni = 0; ni < 4; ni++)
#pragma unroll
            for (int r = 0; r < 4; r++) acc[mi][ni][r] = 0.0f;

    int nt = K >> 6;

#define FLOAD_TILE(t)                                                          \
    do {                                                                       \
        uint32_t oa_ = (uint32_t)((t) & 1) * FA_B;                             \
        uint32_t ob_ = (uint32_t)((t) & 1) * FB_B;                             \
        int k0_ = (t) << 6;                                                    \
        _Pragma("unroll")                                                      \
        for (int i_ = 0; i_ < 2; i_++)                                         \
            cpa16(aBase + oa_ + (uint32_t)aRowc[i_] * ROWB + (uint32_t)aChoff[i_] * 2, \
                  Ab + (size_t)aRowc[i_] * K + k0_ + aChoff[i_]);              \
        _Pragma("unroll")                                                      \
        for (int i_ = 0; i_ < 8; i_++)                                         \
            cpa16(bBase + ob_ + (uint32_t)bRowc[i_] * ROWB + (uint32_t)bChoff[i_] * 2, \
                  B + (size_t)bRowc[i_] * K + k0_ + bChoff[i_]);               \
        cpa_commit();                                                          \
    } while (0)

    FLOAD_TILE(0);

    for (int j = 0; j < nt; j++) {
        cpa_wait0();
        __syncthreads();
        if (j + 1 < nt) FLOAD_TILE(j + 1);

        uint32_t aOff = (uint32_t)(j & 1) * FA_B;
        uint32_t bOff = (uint32_t)(j & 1) * FB_B;
#pragma unroll
        for (int ks = 0; ks < 4; ks++) {
            uint32_t kb = (uint32_t)(ks * 32);
            uint32_t af[4][4], bf[4][2];
#pragma unroll
            for (int mi = 0; mi < 4; mi++)
                ldsm4(af[mi][0], af[mi][1], af[mi][2], af[mi][3],
                      aAddr + aOff + kb + (uint32_t)(mi * 16) * ROWB);
#pragma unroll
            for (int pi = 0; pi < 2; pi++)
                ldsm4(bf[2 * pi][0], bf[2 * pi][1], bf[2 * pi + 1][0], bf[2 * pi + 1][1],
                      bAddr + bOff + kb + (uint32_t)(pi * 16) * ROWB);
#pragma unroll
            for (int mi = 0; mi < 4; mi++)
#pragma unroll
                for (int ni = 0; ni < 4; ni++)
                    mma_bf16(acc[mi][ni], af[mi], bf[ni]);
        }
    }
    __syncthreads();

    float* stage = (float*)smem;
#pragma unroll
    for (int mi = 0; mi < 4; mi++) {
        int r0 = mi * 16 + grp;
#pragma unroll
        for (int ni = 0; ni < 4; ni++) {
            int c = wn + ni * 8 + tig * 2;
            float bv0 = __ldg(bias + c), bv1 = __ldg(bias + c + 1);
            stage[r0 * STG_S + c]           = acc[mi][ni][0] + bv0;
            stage[r0 * STG_S + c + 1]       = acc[mi][ni][1] + bv1;
            stage[(r0 + 8) * STG_S + c]     = acc[mi][ni][2] + bv0;
            stage[(r0 + 8) * STG_S + c + 1] = acc[mi][ni][3] + bv1;
        }
    }
    __syncthreads();

    float4 sv0 = *(const float4*)(lns + lane * 8);
    float4 sv1 = *(const float4*)(lns + lane * 8 + 4);
    float4 bv0 = *(const float4*)(lnb + lane * 8);
    float4 bv1 = *(const float4*)(lnb + lane * 8 + 4);
    float sc[8] = {sv0.x, sv0.y, sv0.z, sv0.w, sv1.x, sv1.y, sv1.z, sv1.w};
    float bi[8] = {bv0.x, bv0.y, bv0.z, bv0.w, bv1.x, bv1.y, bv1.z, bv1.w};

#pragma unroll
    for (int it = 0; it < 8; it++) {
        int tok = warp * 8 + it;
        size_t gbase = ((size_t)blockIdx.x * 64 + tok) * DMODEL + lane * 8;
        const float* sp = stage + tok * STG_S + lane * 8;

        float4 xv0 = *(const float4*)(x + gbase);
        float4 xv1 = *(const float4*)(x + gbase + 4);
        float v[8] = {xv0.x + sp[0], xv0.y + sp[1], xv0.z + sp[2], xv0.w + sp[3],
                      xv1.x + sp[4], xv1.y + sp[5], xv1.z + sp[6], xv1.w + sp[7]};

        float sum = 0.0f;
#pragma unroll
        for (int i = 0; i < 8; i++) sum += v[i];
#pragma unroll
        for (int o = 16; o > 0; o >>= 1) sum += __shfl_xor_sync(0xffffffffu, sum, o);
        float m = sum * (1.0f / 256.0f);

        float vs = 0.0f;
#pragma unroll
        for (int i = 0; i < 8; i++) { float d = v[i] - m; vs += d * d; }
#pragma unroll
        for (int o = 16; o > 0; o >>= 1) vs += __shfl_xor_sync(0xffffffffu, vs, o);
        float rstd = rsqrtf(vs * (1.0f / 256.0f) + 1e-5f);

        float o_[8];
#pragma unroll
        for (int i = 0; i < 8; i++) o_[i] = (v[i] - m) * rstd * sc[i] + bi[i];

        float4 w0 = {o_[0], o_[1], o_[2], o_[3]};
        float4 w1 = {o_[4], o_[5], o_[6], o_[7]};
        *(float4*)(x + gbase) = w0;
        *(float4*)(x + gbase + 4) = w1;
#pragma unroll
        for (int i = 0; i < 8; i += 2) {
            __nv_bfloat162 c2 = {__float2bfloat16_rn(o_[i]), __float2bfloat16_rn(o_[i + 1])};
            *(__nv_bfloat162*)(xb + gbase + i) = c2;
        }
    }
}

// ---------------------------------------------------------------------------
// Tensor-core windowed attention (fp16 mma, fp32 softmax).
// ---------------------------------------------------------------------------
#define ATT_RS   40
#define ATT_MATH (64 * ATT_RS)
#define ATT_WARPH (2 * ATT_MATH)
#define ATT_SMEM (4 * ATT_WARPH * 2)

__global__ void __launch_bounds__(128, 4)
attn_tc(const __half* __restrict__ qkv, __nv_bfloat16* __restrict__ att)
{
    extern __shared__ __half ash[];
    int tid = threadIdx.x, warp = tid >> 5, lane = tid & 31;
    int w = blockIdx.x;
    int head = blockIdx.y * 4 + warp;
    int grp = lane >> 2, tig = lane & 3;

    __half* base = ash + warp * ATT_WARPH;
    uint32_t sb = (uint32_t)__cvta_generic_to_shared(base);

    const __half* src = qkv + (size_t)w * 64 * DQKV + head * 32;
#pragma unroll
    for (int m = 0; m < 2; m++) {
        const __half* ms = src + 256 + m * 256;
        __half* dst = base + m * ATT_MATH;
#pragma unroll
        for (int p = 0; p < 8; p++) {
            int c = p * 32 + lane;
            int row = c >> 2, ch = c & 3;
            *(uint4*)(dst + row * ATT_RS + ch * 8) =
                *(const uint4*)(ms + (size_t)row * DQKV + ch * 8);
        }
    }
    __syncwarp();

    const uint32_t Ks = sb;
    const uint32_t Vs = sb + ATT_MATH * 2;
    const __half* qbase = src;

    const float scale = 0.17677669529663687f;

#pragma unroll
    for (int qt = 0; qt < 4; qt++) {
        uint32_t qa[2][4];
#pragma unroll
        for (int ks = 0; ks < 2; ks++) {
            const __half* qp = qbase + (size_t)(qt * 16 + grp) * DQKV + ks * 16 + tig * 2;
            qa[ks][0] = *(const uint32_t*)(qp);
            qa[ks][1] = *(const uint32_t*)(qp + 8 * DQKV);
            qa[ks][2] = *(const uint32_t*)(qp + 8);
            qa[ks][3] = *(const uint32_t*)(qp + 8 * DQKV + 8);
        }

        float s[8][4];
#pragma unroll
        for (int nt2 = 0; nt2 < 8; nt2++)
#pragma unroll
            for (int r = 0; r < 4; r++) s[nt2][r] = 0.0f;

#pragma unroll
        for (int ks = 0; ks < 2; ks++) {
            uint32_t kf[8][2];
#pragma unroll
            for (int pi = 0; pi < 4; pi++) {
                uint32_t addr = Ks +
                    (uint32_t)((pi * 16 + (lane >> 4) * 8 + (lane & 7)) * ATT_RS +
                               ((lane >> 3) & 1) * 8 + ks * 16) * 2;
                ldsm4(kf[2 * pi][0], kf[2 * pi][1],
                      kf[2 * pi + 1][0], kf[2 * pi + 1][1], addr);
            }
#pragma unroll
            for (int nt2 = 0; nt2 < 8; nt2++)
                mma_fp16(s[nt2], qa[ks], kf[nt2]);
        }

        float mx0 = -1e30f, mx1 = -1e30f;
#pragma unroll
        for (int nt2 = 0; nt2 < 8; nt2++) {
            s[nt2][0] *= scale; s[nt2][1] *= scale;
            s[nt2][2] *= scale; s[nt2][3] *= scale;
            mx0 = fmaxf(mx0, fmaxf(s[nt2][0], s[nt2][1]));
            mx1 = fmaxf(mx1, fmaxf(s[nt2][2], s[nt2][3]));
        }
        mx0 = fmaxf(mx0, __shfl_xor_sync(0xffffffffu, mx0, 1));
        mx0 = fmaxf(mx0, __shfl_xor_sync(0xffffffffu, mx0, 2));
        mx1 = fmaxf(mx1, __shfl_xor_sync(0xffffffffu, mx1, 1));
        mx1 = fmaxf(mx1, __shfl_xor_sync(0xffffffffu, mx1, 2));

        float sm0 = 0.0f, sm1 = 0.0f;
#pragma unroll
        for (int nt2 = 0; nt2 < 8; nt2++) {
            s[nt2][0] = expf(s[nt2][0] - mx0);
            s[nt2][1] = expf(s[nt2][1] - mx0);
            s[nt2][2] = expf(s[nt2][2] - mx1);
            s[nt2][3] = expf(s[nt2][3] - mx1);
            sm0 += s[nt2][0] + s[nt2][1];
            sm1 += s[nt2][2] + s[nt2][3];
        }
        sm0 += __shfl_xor_sync(0xffffffffu, sm0, 1);
        sm0 += __shfl_xor_sync(0xffffffffu, sm0, 2);
        sm1 += __shfl_xor_sync(0xffffffffu, sm1, 1);
        sm1 += __shfl_xor_sync(0xffffffffu, sm1, 2);
        float inv0 = 1.0f / sm0, inv1 = 1.0f / sm1;

        uint32_t pa[4][4];
#pragma unroll
        for (int ks2 = 0; ks2 < 4; ks2++) {
            pa[ks2][0] = packh2(s[2 * ks2][0],     s[2 * ks2][1]);
            pa[ks2][1] = packh2(s[2 * ks2][2],     s[2 * ks2][3]);
            pa[ks2][2] = packh2(s[2 * ks2 + 1][0], s[2 * ks2 + 1][1]);
            pa[ks2][3] = packh2(s[2 * ks2 + 1][2], s[2 * ks2 + 1][3]);
        }

        float o[4][4];
#pragma unroll
        for (int nt2 = 0; nt2 < 4; nt2++)
#pragma unroll
            for (int r = 0; r < 4; r++) o[nt2][r] = 0.0f;

#pragma unroll
        for (int ks2 = 0; ks2 < 4; ks2++) {
            uint32_t vf[4][2];
#pragma unroll
            for (int np = 0; np < 2; np++) {
                uint32_t addr = Vs +
                    (uint32_t)((ks2 * 16 + ((lane >> 3) & 1) * 8 + (lane & 7)) * ATT_RS +
                               ((lane >> 4) + np * 2) * 8) * 2;
                ldsm4t(vf[2 * np][0], vf[2 * np][1],
                       vf[2 * np + 1][0], vf[2 * np + 1][1], addr);
            }
#pragma unroll
            for (int nt2 = 0; nt2 < 4; nt2++)
                mma_fp16(o[nt2], pa[ks2], vf[nt2]);
        }

        int row0 = w * 64 + qt * 16 + grp;
        __nv_bfloat16* ob = att + (size_t)row0 * DMODEL + head * 32 + tig * 2;
#pragma unroll
        for (int nt2 = 0; nt2 < 4; nt2++) {
            __nv_bfloat162 p0 = {__float2bfloat16_rn(o[nt2][0] * inv0),
                                 __float2bfloat16_rn(o[nt2][1] * inv0)};
            __nv_bfloat162 p1 = {__float2bfloat16_rn(o[nt2][2] * inv1),
                                 __float2bfloat16_rn(o[nt2][3] * inv1)};
            *(__nv_bfloat162*)(ob + nt2 * 8) = p0;
            *(__nv_bfloat162*)(ob + 8 * DMODEL + nt2 * 8) = p1;
        }
    }
}

// ---------------------------------------------------------------------------
// Final LN + transposed, fully-coalesced write to [B, C, H*W].
// ---------------------------------------------------------------------------
__global__ __launch_bounds__(256)
void final_ln_t(const float* __restrict__ x, const float* __restrict__ s,
                const float* __restrict__ b, float* __restrict__ out)
{
    __shared__ float stage[32][257];
    int bb = blockIdx.y, l0 = blockIdx.x * 32;
    int warp = threadIdx.x >> 5, lane = threadIdx.x & 31;

    float4 sv0 = *(const float4*)(s + lane * 8);
    float4 sv1 = *(const float4*)(s + lane * 8 + 4);
    float4 bv0 = *(const float4*)(b + lane * 8);
    float4 bv1 = *(const float4*)(b + lane * 8 + 4);
    float sc[8] = {sv0.x, sv0.y, sv0.z, sv0.w, sv1.x, sv1.y, sv1.z, sv1.w};
    float bi[8] = {bv0.x, bv0.y, bv0.z, bv0.w, bv1.x, bv1.y, bv1.z, bv1.w};

#pragma unroll
    for (int it = 0; it < 4; it++) {
        int tl = warp * 4 + it;
        size_t base = ((size_t)(bb * 1024 + l0 + tl)) * DMODEL + lane * 8;
        float4 v0 = *(const float4*)(x + base);
        float4 v1 = *(const float4*)(x + base + 4);
        float v[8] = {v0.x, v0.y, v0.z, v0.w, v1.x, v1.y, v1.z, v1.w};

        float sum = 0.0f;
#pragma unroll
        for (int i = 0; i < 8; i++) sum += v[i];
#pragma unroll
        for (int o = 16; o > 0; o >>= 1) sum += __shfl_xor_sync(0xffffffffu, sum, o);
        float m = sum * (1.0f / 256.0f);

        float vs = 0.0f;
#pragma unroll
        for (int i = 0; i < 8; i++) { float d = v[i] - m; vs += d * d; }
#pragma unroll
        for (int o = 16; o > 0; o >>= 1) vs += __shfl_xor_sync(0xffffffffu, vs, o);
        float rstd = rsqrtf(vs * (1.0f / 256.0f) + 1e-5f);

#pragma unroll
        for (int i = 0; i < 8; i++)
            stage[tl][lane * 8 + i] = (v[i] - m) * rstd * sc[i] + bi[i];
    }
    __syncthreads();

#pragma unroll
    for (int dd = warp; dd < DMODEL; dd += 8)
        out[((size_t)bb * DMODEL + dd) * 1024 + l0 + lane] = stage[lane][dd];
}

// ---------------------------------------------------------------------------
extern "C" void kernel_launch(void* const* d_in, const int* in_sizes, int n_in,
                              void* d_out, int out_size)
{
    const float* features = (const float*)d_in[0];
    const float* in_w  = (const float*)d_in[1];
    const float* in_b  = (const float*)d_in[2];
    const float* ow    = (const float*)d_in[3];
    const float* ob    = (const float*)d_in[4];
    const float* w1    = (const float*)d_in[5];
    const float* b1    = (const float*)d_in[6];
    const float* w2    = (const float*)d_in[7];
    const float* b2    = (const float*)d_in[8];
    const float* ln1s  = (const float*)d_in[9];
    const float* ln1b  = (const float*)d_in[10];
    const float* ln2s  = (const float*)d_in[11];
    const float* ln2b  = (const float*)d_in[12];
    const float* fns   = (const float*)d_in[13];
    const float* fnb   = (const float*)d_in[14];
    float* out = (float*)d_out;

    float* x;
    __half* qkvh;
    __nv_bfloat16 *xb, *att, *hh, *wb;
    cudaGetSymbolAddress((void**)&x,    g_x);
    cudaGetSymbolAddress((void**)&xb,   g_xb);
    cudaGetSymbolAddress((void**)&qkvh, g_qkv);
    cudaGetSymbolAddress((void**)&att,  g_att);
    cudaGetSymbolAddress((void**)&hh,   g_h);
    cudaGetSymbolAddress((void**)&wb,   g_wb);

    cudaFuncSetAttribute(gemm_wide, cudaFuncAttributeMaxDynamicSharedMemorySize, WG_SMEM);
    cudaFuncSetAttribute(gemm_ln,   cudaFuncAttributeMaxDynamicSharedMemorySize, FG_SMEM);
    cudaFuncSetAttribute(attn_tc,   cudaFuncAttributeMaxDynamicSharedMemorySize, ATT_SMEM);

    cvt_all<<<(CV4 + 255) / 256, 256>>>(in_w, ow, w1, w2, wb);

    dim3 eb(32, 32);
    dim3 eg(32, 8, 32);
    embed_kernel<<<eg, eb>>>(features, x, xb);

    const int T = T_TOK;
    for (int i = 0; i < 3; i++) {
        gemm_wide<<<dim3(DQKV / 256, T / 128), 256, WG_SMEM>>>(
            xb, wb + WT_INW + (size_t)i * DQKV * DMODEL, in_b + (size_t)i * DQKV,
            nullptr, qkvh, T, DQKV, DMODEL, 0, 2);
        attn_tc<<<dim3(512, 2), 128, ATT_SMEM>>>(qkvh, att);
        gemm_ln<<<T / 64, 256, FG_SMEM>>>(
            att, wb + WT_OW + (size_t)i * DMODEL * DMODEL, ob + (size_t)i * DMODEL,
            ln1s + (size_t)i * DMODEL, ln1b + (size_t)i * DMODEL, x, xb, DMODEL);
        gemm_wide<<<dim3(DFFN / 256, T / 128), 256, WG_SMEM>>>(
            xb, wb + WT_W1 + (size_t)i * DFFN * DMODEL, b1 + (size_t)i * DFFN,
            hh, nullptr, T, DFFN, DMODEL, 1, 1);
        gemm_ln<<<T / 64, 256, FG_SMEM>>>(
            hh, wb + WT_W2 + (size_t)i * DMODEL * DFFN, b2 + (size_t)i * DMODEL,
            ln2s + (size_t)i * DMODEL, ln2b + (size_t)i * DMODEL, x, xb, DFFN);
    }
    final_ln_t<<<dim3(32, 32), 256>>>(x, fns, fnb, out);
}

// round 14
// speedup vs baseline: 1.1590x; 1.1590x over previous
#include <cuda_runtime.h>
#include <cuda_bf16.h>
#include <cuda_fp16.h>
#include <math.h>
#include <stdint.h>

// ---------------------------------------------------------------------------
// EfficientTransformerEncoder: B=32, D=256 -> L=1024, NH=8, NL=3, DFF=1024,
// WIN=64. bf16 mma.sync GEMMs (3-stage cp.async) + fp16 TC attention + fused LN.
// (R12 configuration restored; wide-tile experiment reverted.)
// ---------------------------------------------------------------------------

#define T_TOK   32768
#define DMODEL  256
#define DQKV    768
#define DFFN    1024

__device__ float          g_x  [(size_t)T_TOK * DMODEL];
__device__ __nv_bfloat16  g_xb [(size_t)T_TOK * DMODEL];
__device__ __half         g_qkv[(size_t)T_TOK * DQKV];
__device__ __nv_bfloat16  g_att[(size_t)T_TOK * DMODEL];
__device__ __nv_bfloat16  g_h  [(size_t)T_TOK * DFFN];

#define WT_INW 0
#define WT_OW  (WT_INW + 3 * DQKV * DMODEL)
#define WT_W1  (WT_OW  + 3 * DMODEL * DMODEL)
#define WT_W2  (WT_W1  + 3 * DFFN * DMODEL)
#define WT_TOT (WT_W2  + 3 * DMODEL * DFFN)
__device__ __nv_bfloat16 g_wb[WT_TOT];

#define CV0 0
#define CV1 (WT_OW  / 4)
#define CV2 (WT_W1  / 4)
#define CV3 (WT_W2  / 4)
#define CV4 (WT_TOT / 4)

// ---------------------------------------------------------------------------
__global__ void cvt_all(const float* __restrict__ s0, const float* __restrict__ s1,
                        const float* __restrict__ s2, const float* __restrict__ s3,
                        __nv_bfloat16* __restrict__ dst) {
    int i = blockIdx.x * blockDim.x + threadIdx.x;
    if (i >= CV4) return;
    const float* src;
    int off;
    if (i < CV1)      { src = s0; off = i - CV0; }
    else if (i < CV2) { src = s1; off = i - CV1; }
    else if (i < CV3) { src = s2; off = i - CV2; }
    else              { src = s3; off = i - CV3; }
    float4 v = ((const float4*)src)[off];
    __nv_bfloat162 lo = {__float2bfloat16_rn(v.x), __float2bfloat16_rn(v.y)};
    __nv_bfloat162 hi = {__float2bfloat16_rn(v.z), __float2bfloat16_rn(v.w)};
    ((__nv_bfloat162*)dst)[i * 2]     = lo;
    ((__nv_bfloat162*)dst)[i * 2 + 1] = hi;
}

// ---------------------------------------------------------------------------
__device__ __forceinline__ float pe_val(int l, int d) {
    int i = d >> 1;
    float freq = expf(-(float)(2 * i) * 0.0359778920439f);
    float ang = (float)l * freq;
    return (d & 1) ? cosf(ang) : sinf(ang);
}

__global__ void embed_kernel(const float* __restrict__ f,
                             float* __restrict__ x, __nv_bfloat16* __restrict__ xb) {
    __shared__ float tile[32][33];
    int b  = blockIdx.z;
    int l0 = blockIdx.x * 32, d0 = blockIdx.y * 32;
    int tx = threadIdx.x, ty = threadIdx.y;
    tile[ty][tx] = f[((size_t)b * DMODEL + d0 + ty) * 1024 + l0 + tx];
    __syncthreads();
    int l = l0 + ty, d = d0 + tx;
    float v = tile[tx][ty] + pe_val(l, d);
    size_t idx = ((size_t)b * 1024 + l) * DMODEL + d;
    x[idx]  = v;
    xb[idx] = __float2bfloat16_rn(v);
}

// ---------------------------------------------------------------------------
__device__ __forceinline__ float gelu_exact(float v) {
    return 0.5f * v * (1.0f + erff(v * 0.7071067811865476f));
}

__device__ __forceinline__ void mma_bf16(float c[4], const uint32_t a[4], const uint32_t b[2]) {
    asm volatile(
        "mma.sync.aligned.m16n8k16.row.col.f32.bf16.bf16.f32 "
        "{%0,%1,%2,%3}, {%4,%5,%6,%7}, {%8,%9}, {%0,%1,%2,%3};\n"
        : "+f"(c[0]), "+f"(c[1]), "+f"(c[2]), "+f"(c[3])
        : "r"(a[0]), "r"(a[1]), "r"(a[2]), "r"(a[3]), "r"(b[0]), "r"(b[1]));
}

__device__ __forceinline__ void mma_fp16(float c[4], const uint32_t a[4], const uint32_t b[2]) {
    asm volatile(
        "mma.sync.aligned.m16n8k16.row.col.f32.f16.f16.f32 "
        "{%0,%1,%2,%3}, {%4,%5,%6,%7}, {%8,%9}, {%0,%1,%2,%3};\n"
        : "+f"(c[0]), "+f"(c[1]), "+f"(c[2]), "+f"(c[3])
        : "r"(a[0]), "r"(a[1]), "r"(a[2]), "r"(a[3]), "r"(b[0]), "r"(b[1]));
}

__device__ __forceinline__ void ldsm4(uint32_t& r0, uint32_t& r1, uint32_t& r2, uint32_t& r3,
                                      uint32_t addr) {
    asm volatile("ldmatrix.sync.aligned.m8n8.x4.shared.b16 {%0,%1,%2,%3}, [%4];"
                 : "=r"(r0), "=r"(r1), "=r"(r2), "=r"(r3) : "r"(addr));
}
__device__ __forceinline__ void ldsm4t(uint32_t& r0, uint32_t& r1, uint32_t& r2, uint32_t& r3,
                                       uint32_t addr) {
    asm volatile("ldmatrix.sync.aligned.m8n8.x4.trans.shared.b16 {%0,%1,%2,%3}, [%4];"
                 : "=r"(r0), "=r"(r1), "=r"(r2), "=r"(r3) : "r"(addr));
}

__device__ __forceinline__ void cpa16(uint32_t dst, const void* src) {
    asm volatile("cp.async.cg.shared.global [%0], [%1], 16;\n" :: "r"(dst), "l"(src));
}
__device__ __forceinline__ void cpa_commit() {
    asm volatile("cp.async.commit_group;\n" ::: "memory");
}
__device__ __forceinline__ void cpa_wait0() {
    asm volatile("cp.async.wait_group 0;\n" ::: "memory");
}
__device__ __forceinline__ void cpa_wait1() {
    asm volatile("cp.async.wait_group 1;\n" ::: "memory");
}

__device__ __forceinline__ uint32_t packh2(float x, float y) {
    __half2 h = __floats2half2_rn(x, y);
    return *reinterpret_cast<uint32_t*>(&h);
}

#define SMH  72
#define ROWB (SMH * 2)

// ---------------------------------------------------------------------------
// Generic 128x128 bf16 GEMM, 3-stage cp.async pipeline.
// ---------------------------------------------------------------------------
#define MATB (128 * ROWB)
#define GSMEM_SZ (6 * MATB)

__global__ void __launch_bounds__(256, 2)
gemm_bf16(const __nv_bfloat16* __restrict__ A, const __nv_bfloat16* __restrict__ B,
          const float* __restrict__ bias,
          __nv_bfloat16* __restrict__ Cb, __half* __restrict__ Ch,
          int M, int N, int K, int act, int outmode)
{
    extern __shared__ __nv_bfloat16 smem[];
    uint32_t sbase = (uint32_t)__cvta_generic_to_shared(smem);
    uint32_t aBase = sbase;
    uint32_t bBase = sbase + 3 * MATB;

    int tid  = threadIdx.x;
    int warp = tid >> 5, lane = tid & 31;
    int wm = (warp >> 2) * 64;
    int wn = (warp & 3) * 32;
    int grp = lane >> 2, tig = lane & 3;

    const __nv_bfloat16* Ab = A + (size_t)blockIdx.y * 128 * K;
    const __nv_bfloat16* Bb = B + (size_t)blockIdx.x * 128 * K;

    int rowc[4], choff[4];
#pragma unroll
    for (int i = 0; i < 4; i++) {
        int c = tid + 256 * i;
        rowc[i]  = c >> 3;
        choff[i] = (c & 7) * 8;
    }

    int aRow = wm + ((lane >> 3) & 1) * 8 + (lane & 7);
    int aK   = (lane >> 4) * 8;
    int bRow = wn + (lane >> 4) * 8 + (lane & 7);
    int bK   = ((lane >> 3) & 1) * 8;
    uint32_t aAddr = aBase + (uint32_t)aRow * ROWB + (uint32_t)aK * 2;
    uint32_t bAddr = bBase + (uint32_t)bRow * ROWB + (uint32_t)bK * 2;

    float acc[4][4][4];
#pragma unroll
    for (int mi = 0; mi < 4; mi++)
#pragma unroll
        for (int ni = 0; ni < 4; ni++)
#pragma unroll
            for (int r = 0; r < 4; r++) acc[mi][ni][r] = 0.0f;

    int nt = K >> 6;

#define LOAD_TILE(t)                                                           \
    do {                                                                       \
        uint32_t off_ = (uint32_t)((t) % 3) * MATB;                            \
        int k0_ = (t) << 6;                                                    \
        _Pragma("unroll")                                                      \
        for (int i_ = 0; i_ < 4; i_++) {                                       \
            uint32_t d_ = off_ + (uint32_t)rowc[i_] * ROWB + (uint32_t)choff[i_] * 2; \
            cpa16(aBase + d_, Ab + (size_t)rowc[i_] * K + k0_ + choff[i_]);    \
            cpa16(bBase + d_, Bb + (size_t)rowc[i_] * K + k0_ + choff[i_]);    \
        }                                                                      \
        cpa_commit();                                                          \
    } while (0)

    LOAD_TILE(0);
    if (nt > 1) LOAD_TILE(1);

    for (int j = 0; j < nt; j++) {
        if (j + 1 < nt) cpa_wait1(); else cpa_wait0();
        __syncthreads();
        if (j + 2 < nt) LOAD_TILE(j + 2);

        uint32_t bufOff = (uint32_t)(j % 3) * MATB;
#pragma unroll
        for (int ks = 0; ks < 4; ks++) {
            uint32_t kOff = bufOff + (uint32_t)(ks * 32);
            uint32_t af[4][4], bf[4][2];
#pragma unroll
            for (int mi = 0; mi < 4; mi++)
                ldsm4(af[mi][0], af[mi][1], af[mi][2], af[mi][3],
                      aAddr + kOff + (uint32_t)(mi * 16) * ROWB);
#pragma unroll
            for (int pi = 0; pi < 2; pi++)
                ldsm4(bf[2 * pi][0], bf[2 * pi][1], bf[2 * pi + 1][0], bf[2 * pi + 1][1],
                      bAddr + kOff + (uint32_t)(pi * 16) * ROWB);
#pragma unroll
            for (int mi = 0; mi < 4; mi++)
#pragma unroll
                for (int ni = 0; ni < 4; ni++)
                    mma_bf16(acc[mi][ni], af[mi], bf[ni]);
        }
    }

#pragma unroll
    for (int mi = 0; mi < 4; mi++) {
        int r0 = blockIdx.y * 128 + wm + mi * 16 + grp;
#pragma unroll
        for (int ni = 0; ni < 4; ni++) {
            int c = blockIdx.x * 128 + wn + ni * 8 + tig * 2;
            float bv0 = __ldg(bias + c), bv1 = __ldg(bias + c + 1);
            float v0 = acc[mi][ni][0] + bv0;
            float v1 = acc[mi][ni][1] + bv1;
            float v2 = acc[mi][ni][2] + bv0;
            float v3 = acc[mi][ni][3] + bv1;
            if (act == 1) {
                v0 = gelu_exact(v0); v1 = gelu_exact(v1);
                v2 = gelu_exact(v2); v3 = gelu_exact(v3);
            }
            if (outmode == 1) {
                __nv_bfloat162 p0 = {__float2bfloat16_rn(v0), __float2bfloat16_rn(v1)};
                __nv_bfloat162 p1 = {__float2bfloat16_rn(v2), __float2bfloat16_rn(v3)};
                *(__nv_bfloat162*)(Cb + (size_t)r0 * N + c) = p0;
                *(__nv_bfloat162*)(Cb + (size_t)(r0 + 8) * N + c) = p1;
            } else {
                uint32_t p0 = packh2(v0, v1), p1 = packh2(v2, v3);
                *(uint32_t*)(Ch + (size_t)r0 * N + c) = p0;
                *(uint32_t*)(Ch + (size_t)(r0 + 8) * N + c) = p1;
            }
        }
    }
}

// ---------------------------------------------------------------------------
// Fused GEMM(N=256) + residual + LayerNorm. Block tile 64x256, 8 warps (1x8).
// wrXb: 0 -> skip bf16 xb write (last layer).
// ---------------------------------------------------------------------------
#define FA_B  (64 * ROWB)
#define FB_B  (256 * ROWB)
#define FG_SMEM (2 * FA_B + 2 * FB_B)
#define STG_S 264

__global__ void __launch_bounds__(256, 2)
gemm_ln(const __nv_bfloat16* __restrict__ A, const __nv_bfloat16* __restrict__ B,
        const float* __restrict__ bias,
        const float* __restrict__ lns, const float* __restrict__ lnb,
        float* __restrict__ x, __nv_bfloat16* __restrict__ xb, int K, int wrXb)
{
    extern __shared__ __nv_bfloat16 smem[];
    uint32_t sbase = (uint32_t)__cvta_generic_to_shared(smem);
    uint32_t aBase = sbase;
    uint32_t bBase = sbase + 2 * FA_B;

    int tid  = threadIdx.x;
    int warp = tid >> 5, lane = tid & 31;
    int wn = warp * 32;
    int grp = lane >> 2, tig = lane & 3;

    const __nv_bfloat16* Ab = A + (size_t)blockIdx.x * 64 * K;

    int aRowc[2], aChoff[2];
#pragma unroll
    for (int i = 0; i < 2; i++) {
        int c = tid + 256 * i;
        aRowc[i]  = c >> 3;
        aChoff[i] = (c & 7) * 8;
    }
    int bRowc[8], bChoff[8];
#pragma unroll
    for (int i = 0; i < 8; i++) {
        int c = tid + 256 * i;
        bRowc[i]  = c >> 3;
        bChoff[i] = (c & 7) * 8;
    }

    int aRow = ((lane >> 3) & 1) * 8 + (lane & 7);
    int aK   = (lane >> 4) * 8;
    int bRow = wn + (lane >> 4) * 8 + (lane & 7);
    int bK   = ((lane >> 3) & 1) * 8;
    uint32_t aAddr = aBase + (uint32_t)aRow * ROWB + (uint32_t)aK * 2;
    uint32_t bAddr = bBase + (uint32_t)bRow * ROWB + (uint32_t)bK * 2;

    float acc[4][4][4];
#pragma unroll
    for (int mi = 0; mi < 4; mi++)
#pragma unroll
        for (int ni = 0; ni < 4; ni++)
#pragma unroll
            for (int r = 0; r < 4; r++) acc[mi][ni][r] = 0.0f;

    int nt = K >> 6;

#define FLOAD_TILE(t)                                                          \
    do {                                                                       \
        uint32_t oa_ = (uint32_t)((t) & 1) * FA_B;                             \
        uint32_t ob_ = (uint32_t)((t) & 1) * FB_B;                             \
        int k0_ = (t) << 6;                                                    \
        _Pragma("unroll")                                                      \
        for (int i_ = 0; i_ < 2; i_++)                                         \
            cpa16(aBase + oa_ + (uint32_t)aRowc[i_] * ROWB + (uint32_t)aChoff[i_] * 2, \
                  Ab + (size_t)aRowc[i_] * K + k0_ + aChoff[i_]);              \
        _Pragma("unroll")                                                      \
        for (int i_ = 0; i_ < 8; i_++)                                         \
            cpa16(bBase + ob_ + (uint32_t)bRowc[i_] * ROWB + (uint32_t)bChoff[i_] * 2, \
                  B + (size_t)bRowc[i_] * K + k0_ + bChoff[i_]);               \
        cpa_commit();                                                          \
    } while (0)

    FLOAD_TILE(0);

    for (int j = 0; j < nt; j++) {
        cpa_wait0();
        __syncthreads();
        if (j + 1 < nt) FLOAD_TILE(j + 1);

        uint32_t aOff = (uint32_t)(j & 1) * FA_B;
        uint32_t bOff = (uint32_t)(j & 1) * FB_B;
#pragma unroll
        for (int ks = 0; ks < 4; ks++) {
            uint32_t kb = (uint32_t)(ks * 32);
            uint32_t af[4][4], bf[4][2];
#pragma unroll
            for (int mi = 0; mi < 4; mi++)
                ldsm4(af[mi][0], af[mi][1], af[mi][2], af[mi][3],
                      aAddr + aOff + kb + (uint32_t)(mi * 16) * ROWB);
#pragma unroll
            for (int pi = 0; pi < 2; pi++)
                ldsm4(bf[2 * pi][0], bf[2 * pi][1], bf[2 * pi + 1][0], bf[2 * pi + 1][1],
                      bAddr + bOff + kb + (uint32_t)(pi * 16) * ROWB);
#pragma unroll
            for (int mi = 0; mi < 4; mi++)
#pragma unroll
                for (int ni = 0; ni < 4; ni++)
                    mma_bf16(acc[mi][ni], af[mi], bf[ni]);
        }
    }
    __syncthreads();

    float* stage = (float*)smem;
#pragma unroll
    for (int mi = 0; mi < 4; mi++) {
        int r0 = mi * 16 + grp;
#pragma unroll
        for (int ni = 0; ni < 4; ni++) {
            int c = wn + ni * 8 + tig * 2;
            float bv0 = __ldg(bias + c), bv1 = __ldg(bias + c + 1);
            stage[r0 * STG_S + c]           = acc[mi][ni][0] + bv0;
            stage[r0 * STG_S + c + 1]       = acc[mi][ni][1] + bv1;
            stage[(r0 + 8) * STG_S + c]     = acc[mi][ni][2] + bv0;
            stage[(r0 + 8) * STG_S + c + 1] = acc[mi][ni][3] + bv1;
        }
    }
    __syncthreads();

    float4 sv0 = *(const float4*)(lns + lane * 8);
    float4 sv1 = *(const float4*)(lns + lane * 8 + 4);
    float4 bv0 = *(const float4*)(lnb + lane * 8);
    float4 bv1 = *(const float4*)(lnb + lane * 8 + 4);
    float sc[8] = {sv0.x, sv0.y, sv0.z, sv0.w, sv1.x, sv1.y, sv1.z, sv1.w};
    float bi[8] = {bv0.x, bv0.y, bv0.z, bv0.w, bv1.x, bv1.y, bv1.z, bv1.w};

#pragma unroll
    for (int it = 0; it < 8; it++) {
        int tok = warp * 8 + it;
        size_t gbase = ((size_t)blockIdx.x * 64 + tok) * DMODEL + lane * 8;
        const float* sp = stage + tok * STG_S + lane * 8;

        float4 xv0 = *(const float4*)(x + gbase);
        float4 xv1 = *(const float4*)(x + gbase + 4);
        float v[8] = {xv0.x + sp[0], xv0.y + sp[1], xv0.z + sp[2], xv0.w + sp[3],
                      xv1.x + sp[4], xv1.y + sp[5], xv1.z + sp[6], xv1.w + sp[7]};

        float sum = 0.0f;
#pragma unroll
        for (int i = 0; i < 8; i++) sum += v[i];
#pragma unroll
        for (int o = 16; o > 0; o >>= 1) sum += __shfl_xor_sync(0xffffffffu, sum, o);
        float m = sum * (1.0f / 256.0f);

        float vs = 0.0f;
#pragma unroll
        for (int i = 0; i < 8; i++) { float d = v[i] - m; vs += d * d; }
#pragma unroll
        for (int o = 16; o > 0; o >>= 1) vs += __shfl_xor_sync(0xffffffffu, vs, o);
        float rstd = rsqrtf(vs * (1.0f / 256.0f) + 1e-5f);

        float o_[8];
#pragma unroll
        for (int i = 0; i < 8; i++) o_[i] = (v[i] - m) * rstd * sc[i] + bi[i];

        float4 w0 = {o_[0], o_[1], o_[2], o_[3]};
        float4 w1 = {o_[4], o_[5], o_[6], o_[7]};
        *(float4*)(x + gbase) = w0;
        *(float4*)(x + gbase + 4) = w1;
        if (wrXb) {
#pragma unroll
            for (int i = 0; i < 8; i += 2) {
                __nv_bfloat162 c2 = {__float2bfloat16_rn(o_[i]), __float2bfloat16_rn(o_[i + 1])};
                *(__nv_bfloat162*)(xb + gbase + i) = c2;
            }
        }
    }
}

// ---------------------------------------------------------------------------
// Tensor-core windowed attention (fp16 mma, fp32 softmax).
// K/V staged in smem per warp; Q fragments loaded directly from gmem.
// ---------------------------------------------------------------------------
#define ATT_RS   40
#define ATT_MATH (64 * ATT_RS)
#define ATT_WARPH (2 * ATT_MATH)
#define ATT_SMEM (4 * ATT_WARPH * 2)

__global__ void __launch_bounds__(128, 4)
attn_tc(const __half* __restrict__ qkv, __nv_bfloat16* __restrict__ att)
{
    extern __shared__ __half ash[];
    int tid = threadIdx.x, warp = tid >> 5, lane = tid & 31;
    int w = blockIdx.x;
    int head = blockIdx.y * 4 + warp;
    int grp = lane >> 2, tig = lane & 3;

    __half* base = ash + warp * ATT_WARPH;
    uint32_t sb = (uint32_t)__cvta_generic_to_shared(base);

    const __half* src = qkv + (size_t)w * 64 * DQKV + head * 32;
#pragma unroll
    for (int m = 0; m < 2; m++) {
        const __half* ms = src + 256 + m * 256;
        __half* dst = base + m * ATT_MATH;
#pragma unroll
        for (int p = 0; p < 8; p++) {
            int c = p * 32 + lane;
            int row = c >> 2, ch = c & 3;
            *(uint4*)(dst + row * ATT_RS + ch * 8) =
                *(const uint4*)(ms + (size_t)row * DQKV + ch * 8);
        }
    }
    __syncwarp();

    const uint32_t Ks = sb;
    const uint32_t Vs = sb + ATT_MATH * 2;
    const __half* qbase = src;

    const float scale = 0.17677669529663687f;

#pragma unroll
    for (int qt = 0; qt < 4; qt++) {
        uint32_t qa[2][4];
#pragma unroll
        for (int ks = 0; ks < 2; ks++) {
            const __half* qp = qbase + (size_t)(qt * 16 + grp) * DQKV + ks * 16 + tig * 2;
            qa[ks][0] = *(const uint32_t*)(qp);
            qa[ks][1] = *(const uint32_t*)(qp + 8 * DQKV);
            qa[ks][2] = *(const uint32_t*)(qp + 8);
            qa[ks][3] = *(const uint32_t*)(qp + 8 * DQKV + 8);
        }

        float s[8][4];
#pragma unroll
        for (int nt2 = 0; nt2 < 8; nt2++)
#pragma unroll
            for (int r = 0; r < 4; r++) s[nt2][r] = 0.0f;

#pragma unroll
        for (int ks = 0; ks < 2; ks++) {
            uint32_t kf[8][2];
#pragma unroll
            for (int pi = 0; pi < 4; pi++) {
                uint32_t addr = Ks +
                    (uint32_t)((pi * 16 + (lane >> 4) * 8 + (lane & 7)) * ATT_RS +
                               ((lane >> 3) & 1) * 8 + ks * 16) * 2;
                ldsm4(kf[2 * pi][0], kf[2 * pi][1],
                      kf[2 * pi + 1][0], kf[2 * pi + 1][1], addr);
            }
#pragma unroll
            for (int nt2 = 0; nt2 < 8; nt2++)
                mma_fp16(s[nt2], qa[ks], kf[nt2]);
        }

        float mx0 = -1e30f, mx1 = -1e30f;
#pragma unroll
        for (int nt2 = 0; nt2 < 8; nt2++) {
            s[nt2][0] *= scale; s[nt2][1] *= scale;
            s[nt2][2] *= scale; s[nt2][3] *= scale;
            mx0 = fmaxf(mx0, fmaxf(s[nt2][0], s[nt2][1]));
            mx1 = fmaxf(mx1, fmaxf(s[nt2][2], s[nt2][3]));
        }
        mx0 = fmaxf(mx0, __shfl_xor_sync(0xffffffffu, mx0, 1));
        mx0 = fmaxf(mx0, __shfl_xor_sync(0xffffffffu, mx0, 2));
        mx1 = fmaxf(mx1, __shfl_xor_sync(0xffffffffu, mx1, 1));
        mx1 = fmaxf(mx1, __shfl_xor_sync(0xffffffffu, mx1, 2));

        float sm0 = 0.0f, sm1 = 0.0f;
#pragma unroll
        for (int nt2 = 0; nt2 < 8; nt2++) {
            s[nt2][0] = expf(s[nt2][0] - mx0);
            s[nt2][1] = expf(s[nt2][1] - mx0);
            s[nt2][2] = expf(s[nt2][2] - mx1);
            s[nt2][3] = expf(s[nt2][3] - mx1);
            sm0 += s[nt2][0] + s[nt2][1];
            sm1 += s[nt2][2] + s[nt2][3];
        }
        sm0 += __shfl_xor_sync(0xffffffffu, sm0, 1);
        sm0 += __shfl_xor_sync(0xffffffffu, sm0, 2);
        sm1 += __shfl_xor_sync(0xffffffffu, sm1, 1);
        sm1 += __shfl_xor_sync(0xffffffffu, sm1, 2);
        float inv0 = 1.0f / sm0, inv1 = 1.0f / sm1;

        uint32_t pa[4][4];
#pragma unroll
        for (int ks2 = 0; ks2 < 4; ks2++) {
            pa[ks2][0] = packh2(s[2 * ks2][0],     s[2 * ks2][1]);
            pa[ks2][1] = packh2(s[2 * ks2][2],     s[2 * ks2][3]);
            pa[ks2][2] = packh2(s[2 * ks2 + 1][0], s[2 * ks2 + 1][1]);
            pa[ks2][3] = packh2(s[2 * ks2 + 1][2], s[2 * ks2 + 1][3]);
        }

        float o[4][4];
#pragma unroll
        for (int nt2 = 0; nt2 < 4; nt2++)
#pragma unroll
            for (int r = 0; r < 4; r++) o[nt2][r] = 0.0f;

#pragma unroll
        for (int ks2 = 0; ks2 < 4; ks2++) {
            uint32_t vf[4][2];
#pragma unroll
            for (int np = 0; np < 2; np++) {
                uint32_t addr = Vs +
                    (uint32_t)((ks2 * 16 + ((lane >> 3) & 1) * 8 + (lane & 7)) * ATT_RS +
                               ((lane >> 4) + np * 2) * 8) * 2;
                ldsm4t(vf[2 * np][0], vf[2 * np][1],
                       vf[2 * np + 1][0], vf[2 * np + 1][1], addr);
            }
#pragma unroll
            for (int nt2 = 0; nt2 < 4; nt2++)
                mma_fp16(o[nt2], pa[ks2], vf[nt2]);
        }

        int row0 = w * 64 + qt * 16 + grp;
        __nv_bfloat16* ob = att + (size_t)row0 * DMODEL + head * 32 + tig * 2;
#pragma unroll
        for (int nt2 = 0; nt2 < 4; nt2++) {
            __nv_bfloat162 p0 = {__float2bfloat16_rn(o[nt2][0] * inv0),
                                 __float2bfloat16_rn(o[nt2][1] * inv0)};
            __nv_bfloat162 p1 = {__float2bfloat16_rn(o[nt2][2] * inv1),
                                 __float2bfloat16_rn(o[nt2][3] * inv1)};
            *(__nv_bfloat162*)(ob + nt2 * 8) = p0;
            *(__nv_bfloat162*)(ob + 8 * DMODEL + nt2 * 8) = p1;
        }
    }
}

// ---------------------------------------------------------------------------
// Final LN + transposed, fully-coalesced write to [B, C, H*W].
// ---------------------------------------------------------------------------
__global__ __launch_bounds__(256)
void final_ln_t(const float* __restrict__ x, const float* __restrict__ s,
                const float* __restrict__ b, float* __restrict__ out)
{
    __shared__ float stage[32][257];
    int bb = blockIdx.y, l0 = blockIdx.x * 32;
    int warp = threadIdx.x >> 5, lane = threadIdx.x & 31;

    float4 sv0 = *(const float4*)(s + lane * 8);
    float4 sv1 = *(const float4*)(s + lane * 8 + 4);
    float4 bv0 = *(const float4*)(b + lane * 8);
    float4 bv1 = *(const float4*)(b + lane * 8 + 4);
    float sc[8] = {sv0.x, sv0.y, sv0.z, sv0.w, sv1.x, sv1.y, sv1.z, sv1.w};
    float bi[8] = {bv0.x, bv0.y, bv0.z, bv0.w, bv1.x, bv1.y, bv1.z, bv1.w};

#pragma unroll
    for (int it = 0; it < 4; it++) {
        int tl = warp * 4 + it;
        size_t base = ((size_t)(bb * 1024 + l0 + tl)) * DMODEL + lane * 8;
        float4 v0 = *(const float4*)(x + base);
        float4 v1 = *(const float4*)(x + base + 4);
        float v[8] = {v0.x, v0.y, v0.z, v0.w, v1.x, v1.y, v1.z, v1.w};

        float sum = 0.0f;
#pragma unroll
        for (int i = 0; i < 8; i++) sum += v[i];
#pragma unroll
        for (int o = 16; o > 0; o >>= 1) sum += __shfl_xor_sync(0xffffffffu, sum, o);
        float m = sum * (1.0f / 256.0f);

        float vs = 0.0f;
#pragma unroll
        for (int i = 0; i < 8; i++) { float d = v[i] - m; vs += d * d; }
#pragma unroll
        for (int o = 16; o > 0; o >>= 1) vs += __shfl_xor_sync(0xffffffffu, vs, o);
        float rstd = rsqrtf(vs * (1.0f / 256.0f) + 1e-5f);

#pragma unroll
        for (int i = 0; i < 8; i++)
            stage[tl][lane * 8 + i] = (v[i] - m) * rstd * sc[i] + bi[i];
    }
    __syncthreads();

#pragma unroll
    for (int dd = warp; dd < DMODEL; dd += 8)
        out[((size_t)bb * DMODEL + dd) * 1024 + l0 + lane] = stage[lane][dd];
}

// ---------------------------------------------------------------------------
extern "C" void kernel_launch(void* const* d_in, const int* in_sizes, int n_in,
                              void* d_out, int out_size)
{
    const float* features = (const float*)d_in[0];
    const float* in_w  = (const float*)d_in[1];
    const float* in_b  = (const float*)d_in[2];
    const float* ow    = (const float*)d_in[3];
    const float* ob    = (const float*)d_in[4];
    const float* w1    = (const float*)d_in[5];
    const float* b1    = (const float*)d_in[6];
    const float* w2    = (const float*)d_in[7];
    const float* b2    = (const float*)d_in[8];
    const float* ln1s  = (const float*)d_in[9];
    const float* ln1b  = (const float*)d_in[10];
    const float* ln2s  = (const float*)d_in[11];
    const float* ln2b  = (const float*)d_in[12];
    const float* fns   = (const float*)d_in[13];
    const float* fnb   = (const float*)d_in[14];
    float* out = (float*)d_out;

    float* x;
    __half* qkvh;
    __nv_bfloat16 *xb, *att, *hh, *wb;
    cudaGetSymbolAddress((void**)&x,    g_x);
    cudaGetSymbolAddress((void**)&xb,   g_xb);
    cudaGetSymbolAddress((void**)&qkvh, g_qkv);
    cudaGetSymbolAddress((void**)&att,  g_att);
    cudaGetSymbolAddress((void**)&hh,   g_h);
    cudaGetSymbolAddress((void**)&wb,   g_wb);

    cudaFuncSetAttribute(gemm_bf16, cudaFuncAttributeMaxDynamicSharedMemorySize, GSMEM_SZ);
    cudaFuncSetAttribute(gemm_ln,   cudaFuncAttributeMaxDynamicSharedMemorySize, FG_SMEM);
    cudaFuncSetAttribute(attn_tc,   cudaFuncAttributeMaxDynamicSharedMemorySize, ATT_SMEM);

    cvt_all<<<(CV4 + 255) / 256, 256>>>(in_w, ow, w1, w2, wb);

    dim3 eb(32, 32);
    dim3 eg(32, 8, 32);
    embed_kernel<<<eg, eb>>>(features, x, xb);

    const int T = T_TOK;
    for (int i = 0; i < 3; i++) {
        gemm_bf16<<<dim3(DQKV / 128, T / 128), 256, GSMEM_SZ>>>(
            xb, wb + WT_INW + (size_t)i * DQKV * DMODEL, in_b + (size_t)i * DQKV,
            nullptr, qkvh, T, DQKV, DMODEL, 0, 2);
        attn_tc<<<dim3(512, 2), 128, ATT_SMEM>>>(qkvh, att);
        gemm_ln<<<T / 64, 256, FG_SMEM>>>(
            att, wb + WT_OW + (size_t)i * DMODEL * DMODEL, ob + (size_t)i * DMODEL,
            ln1s + (size_t)i * DMODEL, ln1b + (size_t)i * DMODEL, x, xb, DMODEL, 1);
        gemm_bf16<<<dim3(DFFN / 128, T / 128), 256, GSMEM_SZ>>>(
            xb, wb + WT_W1 + (size_t)i * DFFN * DMODEL, b1 + (size_t)i * DFFN,
            hh, nullptr, T, DFFN, DMODEL, 1, 1);
        gemm_ln<<<T / 64, 256, FG_SMEM>>>(
            hh, wb + WT_W2 + (size_t)i * DMODEL * DFFN, b2 + (size_t)i * DMODEL,
            ln2s + (size_t)i * DMODEL, ln2b + (size_t)i * DMODEL, x, xb, DFFN,
            (i < 2) ? 1 : 0);
    }
    final_ln_t<<<dim3(32, 32), 256>>>(x, fns, fnb, out);
}

// round 15
// speedup vs baseline: 1.2027x; 1.0378x over previous
#include <cuda_runtime.h>
#include <cuda_bf16.h>
#include <cuda_fp16.h>
#include <math.h>
#include <stdint.h>

// ---------------------------------------------------------------------------
// EfficientTransformerEncoder: B=32, D=256 -> L=1024, NH=8, NL=3, DFF=1024,
// WIN=64. bf16 mma.sync GEMMs (3-stage cp.async, compile-time trip counts)
// + fp16 TC attention + fused LN epilogues.
// ---------------------------------------------------------------------------

#define T_TOK   32768
#define DMODEL  256
#define DQKV    768
#define DFFN    1024

__device__ float          g_x  [(size_t)T_TOK * DMODEL];
__device__ __nv_bfloat16  g_xb [(size_t)T_TOK * DMODEL];
__device__ __half         g_qkv[(size_t)T_TOK * DQKV];
__device__ __nv_bfloat16  g_att[(size_t)T_TOK * DMODEL];
__device__ __nv_bfloat16  g_h  [(size_t)T_TOK * DFFN];

#define WT_INW 0
#define WT_OW  (WT_INW + 3 * DQKV * DMODEL)
#define WT_W1  (WT_OW  + 3 * DMODEL * DMODEL)
#define WT_W2  (WT_W1  + 3 * DFFN * DMODEL)
#define WT_TOT (WT_W2  + 3 * DMODEL * DFFN)
__device__ __nv_bfloat16 g_wb[WT_TOT];

#define CV0 0
#define CV1 (WT_OW  / 4)
#define CV2 (WT_W1  / 4)
#define CV3 (WT_W2  / 4)
#define CV4 (WT_TOT / 4)

// ---------------------------------------------------------------------------
__global__ void cvt_all(const float* __restrict__ s0, const float* __restrict__ s1,
                        const float* __restrict__ s2, const float* __restrict__ s3,
                        __nv_bfloat16* __restrict__ dst) {
    int i = blockIdx.x * blockDim.x + threadIdx.x;
    if (i >= CV4) return;
    const float* src;
    int off;
    if (i < CV1)      { src = s0; off = i - CV0; }
    else if (i < CV2) { src = s1; off = i - CV1; }
    else if (i < CV3) { src = s2; off = i - CV2; }
    else              { src = s3; off = i - CV3; }
    float4 v = ((const float4*)src)[off];
    __nv_bfloat162 lo = {__float2bfloat16_rn(v.x), __float2bfloat16_rn(v.y)};
    __nv_bfloat162 hi = {__float2bfloat16_rn(v.z), __float2bfloat16_rn(v.w)};
    ((__nv_bfloat162*)dst)[i * 2]     = lo;
    ((__nv_bfloat162*)dst)[i * 2 + 1] = hi;
}

// ---------------------------------------------------------------------------
__device__ __forceinline__ float pe_val(int l, int d) {
    int i = d >> 1;
    float freq = expf(-(float)(2 * i) * 0.0359778920439f);
    float ang = (float)l * freq;
    return (d & 1) ? cosf(ang) : sinf(ang);
}

__global__ void embed_kernel(const float* __restrict__ f,
                             float* __restrict__ x, __nv_bfloat16* __restrict__ xb) {
    __shared__ float tile[32][33];
    int b  = blockIdx.z;
    int l0 = blockIdx.x * 32, d0 = blockIdx.y * 32;
    int tx = threadIdx.x, ty = threadIdx.y;
    tile[ty][tx] = f[((size_t)b * DMODEL + d0 + ty) * 1024 + l0 + tx];
    __syncthreads();
    int l = l0 + ty, d = d0 + tx;
    float v = tile[tx][ty] + pe_val(l, d);
    size_t idx = ((size_t)b * 1024 + l) * DMODEL + d;
    x[idx]  = v;
    xb[idx] = __float2bfloat16_rn(v);
}

// ---------------------------------------------------------------------------
__device__ __forceinline__ float gelu_exact(float v) {
    return 0.5f * v * (1.0f + erff(v * 0.7071067811865476f));
}

__device__ __forceinline__ void mma_bf16(float c[4], const uint32_t a[4], const uint32_t b[2]) {
    asm volatile(
        "mma.sync.aligned.m16n8k16.row.col.f32.bf16.bf16.f32 "
        "{%0,%1,%2,%3}, {%4,%5,%6,%7}, {%8,%9}, {%0,%1,%2,%3};\n"
        : "+f"(c[0]), "+f"(c[1]), "+f"(c[2]), "+f"(c[3])
        : "r"(a[0]), "r"(a[1]), "r"(a[2]), "r"(a[3]), "r"(b[0]), "r"(b[1]));
}

__device__ __forceinline__ void mma_fp16(float c[4], const uint32_t a[4], const uint32_t b[2]) {
    asm volatile(
        "mma.sync.aligned.m16n8k16.row.col.f32.f16.f16.f32 "
        "{%0,%1,%2,%3}, {%4,%5,%6,%7}, {%8,%9}, {%0,%1,%2,%3};\n"
        : "+f"(c[0]), "+f"(c[1]), "+f"(c[2]), "+f"(c[3])
        : "r"(a[0]), "r"(a[1]), "r"(a[2]), "r"(a[3]), "r"(b[0]), "r"(b[1]));
}

__device__ __forceinline__ void ldsm4(uint32_t& r0, uint32_t& r1, uint32_t& r2, uint32_t& r3,
                                      uint32_t addr) {
    asm volatile("ldmatrix.sync.aligned.m8n8.x4.shared.b16 {%0,%1,%2,%3}, [%4];"
                 : "=r"(r0), "=r"(r1), "=r"(r2), "=r"(r3) : "r"(addr));
}
__device__ __forceinline__ void ldsm4t(uint32_t& r0, uint32_t& r1, uint32_t& r2, uint32_t& r3,
                                       uint32_t addr) {
    asm volatile("ldmatrix.sync.aligned.m8n8.x4.trans.shared.b16 {%0,%1,%2,%3}, [%4];"
                 : "=r"(r0), "=r"(r1), "=r"(r2), "=r"(r3) : "r"(addr));
}

__device__ __forceinline__ void cpa16(uint32_t dst, const void* src) {
    asm volatile("cp.async.cg.shared.global [%0], [%1], 16;\n" :: "r"(dst), "l"(src));
}
__device__ __forceinline__ void cpa_commit() {
    asm volatile("cp.async.commit_group;\n" ::: "memory");
}
__device__ __forceinline__ void cpa_wait0() {
    asm volatile("cp.async.wait_group 0;\n" ::: "memory");
}
__device__ __forceinline__ void cpa_wait1() {
    asm volatile("cp.async.wait_group 1;\n" ::: "memory");
}

__device__ __forceinline__ uint32_t packh2(float x, float y) {
    __half2 h = __floats2half2_rn(x, y);
    return *reinterpret_cast<uint32_t*>(&h);
}

#define SMH  72
#define ROWB (SMH * 2)

// ---------------------------------------------------------------------------
// 128x128 bf16 GEMM, 3-stage cp.async pipeline, compile-time NT tiles (K=NT*64).
// outmode: 1 -> bf16 Cb, 2 -> fp16 Ch.
// ---------------------------------------------------------------------------
#define MATB (128 * ROWB)
#define GSMEM_SZ (6 * MATB)

template<int NT>
__global__ void __launch_bounds__(256, 2)
gemm_bf16(const __nv_bfloat16* __restrict__ A, const __nv_bfloat16* __restrict__ B,
          const float* __restrict__ bias,
          __nv_bfloat16* __restrict__ Cb, __half* __restrict__ Ch,
          int M, int N, int act, int outmode)
{
    constexpr int K = NT * 64;
    extern __shared__ __nv_bfloat16 smem[];
    uint32_t sbase = (uint32_t)__cvta_generic_to_shared(smem);
    uint32_t aBase = sbase;
    uint32_t bBase = sbase + 3 * MATB;

    int tid  = threadIdx.x;
    int warp = tid >> 5, lane = tid & 31;
    int wm = (warp >> 2) * 64;
    int wn = (warp & 3) * 32;
    int grp = lane >> 2, tig = lane & 3;

    const __nv_bfloat16* Ab = A + (size_t)blockIdx.y * 128 * K;
    const __nv_bfloat16* Bb = B + (size_t)blockIdx.x * 128 * K;

    int rowc[4], choff[4];
#pragma unroll
    for (int i = 0; i < 4; i++) {
        int c = tid + 256 * i;
        rowc[i]  = c >> 3;
        choff[i] = (c & 7) * 8;
    }

    int aRow = wm + ((lane >> 3) & 1) * 8 + (lane & 7);
    int aK   = (lane >> 4) * 8;
    int bRow = wn + (lane >> 4) * 8 + (lane & 7);
    int bK   = ((lane >> 3) & 1) * 8;
    uint32_t aAddr = aBase + (uint32_t)aRow * ROWB + (uint32_t)aK * 2;
    uint32_t bAddr = bBase + (uint32_t)bRow * ROWB + (uint32_t)bK * 2;

    float acc[4][4][4];
#pragma unroll
    for (int mi = 0; mi < 4; mi++)
#pragma unroll
        for (int ni = 0; ni < 4; ni++)
#pragma unroll
            for (int r = 0; r < 4; r++) acc[mi][ni][r] = 0.0f;

#define LOAD_TILE(t)                                                           \
    do {                                                                       \
        uint32_t off_ = (uint32_t)((t) % 3) * MATB;                            \
        int k0_ = (t) << 6;                                                    \
        _Pragma("unroll")                                                      \
        for (int i_ = 0; i_ < 4; i_++) {                                       \
            uint32_t d_ = off_ + (uint32_t)rowc[i_] * ROWB + (uint32_t)choff[i_] * 2; \
            cpa16(aBase + d_, Ab + (size_t)rowc[i_] * K + k0_ + choff[i_]);    \
            cpa16(bBase + d_, Bb + (size_t)rowc[i_] * K + k0_ + choff[i_]);    \
        }                                                                      \
        cpa_commit();                                                          \
    } while (0)

    LOAD_TILE(0);
    if (NT > 1) LOAD_TILE(1);

#pragma unroll
    for (int j = 0; j < NT; j++) {
        if (j + 1 < NT) cpa_wait1(); else cpa_wait0();
        __syncthreads();
        if (j + 2 < NT) LOAD_TILE(j + 2);

        uint32_t bufOff = (uint32_t)(j % 3) * MATB;
#pragma unroll
        for (int ks = 0; ks < 4; ks++) {
            uint32_t kOff = bufOff + (uint32_t)(ks * 32);
            uint32_t af[4][4], bf[4][2];
#pragma unroll
            for (int mi = 0; mi < 4; mi++)
                ldsm4(af[mi][0], af[mi][1], af[mi][2], af[mi][3],
                      aAddr + kOff + (uint32_t)(mi * 16) * ROWB);
#pragma unroll
            for (int pi = 0; pi < 2; pi++)
                ldsm4(bf[2 * pi][0], bf[2 * pi][1], bf[2 * pi + 1][0], bf[2 * pi + 1][1],
                      bAddr + kOff + (uint32_t)(pi * 16) * ROWB);
#pragma unroll
            for (int mi = 0; mi < 4; mi++)
#pragma unroll
                for (int ni = 0; ni < 4; ni++)
                    mma_bf16(acc[mi][ni], af[mi], bf[ni]);
        }
    }

#pragma unroll
    for (int mi = 0; mi < 4; mi++) {
        int r0 = blockIdx.y * 128 + wm + mi * 16 + grp;
#pragma unroll
        for (int ni = 0; ni < 4; ni++) {
            int c = blockIdx.x * 128 + wn + ni * 8 + tig * 2;
            float bv0 = __ldg(bias + c), bv1 = __ldg(bias + c + 1);
            float v0 = acc[mi][ni][0] + bv0;
            float v1 = acc[mi][ni][1] + bv1;
            float v2 = acc[mi][ni][2] + bv0;
            float v3 = acc[mi][ni][3] + bv1;
            if (act == 1) {
                v0 = gelu_exact(v0); v1 = gelu_exact(v1);
                v2 = gelu_exact(v2); v3 = gelu_exact(v3);
            }
            if (outmode == 1) {
                __nv_bfloat162 p0 = {__float2bfloat16_rn(v0), __float2bfloat16_rn(v1)};
                __nv_bfloat162 p1 = {__float2bfloat16_rn(v2), __float2bfloat16_rn(v3)};
                *(__nv_bfloat162*)(Cb + (size_t)r0 * N + c) = p0;
                *(__nv_bfloat162*)(Cb + (size_t)(r0 + 8) * N + c) = p1;
            } else {
                uint32_t p0 = packh2(v0, v1), p1 = packh2(v2, v3);
                *(uint32_t*)(Ch + (size_t)r0 * N + c) = p0;
                *(uint32_t*)(Ch + (size_t)(r0 + 8) * N + c) = p1;
            }
        }
    }
}

// ---------------------------------------------------------------------------
// Fused GEMM(N=256) + residual + LayerNorm. Block tile 64x256, 8 warps (1x8).
// Compile-time NT tiles (K=NT*64). wrXb: 0 -> skip bf16 xb write.
// ---------------------------------------------------------------------------
#define FA_B  (64 * ROWB)
#define FB_B  (256 * ROWB)
#define FG_SMEM (2 * FA_B + 2 * FB_B)
#define STG_S 264

template<int NT>
__global__ void __launch_bounds__(256, 2)
gemm_ln(const __nv_bfloat16* __restrict__ A, const __nv_bfloat16* __restrict__ B,
        const float* __restrict__ bias,
        const float* __restrict__ lns, const float* __restrict__ lnb,
        float* __restrict__ x, __nv_bfloat16* __restrict__ xb, int wrXb)
{
    constexpr int K = NT * 64;
    extern __shared__ __nv_bfloat16 smem[];
    uint32_t sbase = (uint32_t)__cvta_generic_to_shared(smem);
    uint32_t aBase = sbase;
    uint32_t bBase = sbase + 2 * FA_B;

    int tid  = threadIdx.x;
    int warp = tid >> 5, lane = tid & 31;
    int wn = warp * 32;
    int grp = lane >> 2, tig = lane & 3;

    const __nv_bfloat16* Ab = A + (size_t)blockIdx.x * 64 * K;

    int aRowc[2], aChoff[2];
#pragma unroll
    for (int i = 0; i < 2; i++) {
        int c = tid + 256 * i;
        aRowc[i]  = c >> 3;
        aChoff[i] = (c & 7) * 8;
    }
    int bRowc[8], bChoff[8];
#pragma unroll
    for (int i = 0; i < 8; i++) {
        int c = tid + 256 * i;
        bRowc[i]  = c >> 3;
        bChoff[i] = (c & 7) * 8;
    }

    int aRow = ((lane >> 3) & 1) * 8 + (lane & 7);
    int aK   = (lane >> 4) * 8;
    int bRow = wn + (lane >> 4) * 8 + (lane & 7);
    int bK   = ((lane >> 3) & 1) * 8;
    uint32_t aAddr = aBase + (uint32_t)aRow * ROWB + (uint32_t)aK * 2;
    uint32_t bAddr = bBase + (uint32_t)bRow * ROWB + (uint32_t)bK * 2;

    float acc[4][4][4];
#pragma unroll
    for (int mi = 0; mi < 4; mi++)
#pragma unroll
        for (int ni = 0; ni < 4; ni++)
#pragma unroll
            for (int r = 0; r < 4; r++) acc[mi][ni][r] = 0.0f;

#define FLOAD_TILE(t)                                                          \
    do {                                                                       \
        uint32_t oa_ = (uint32_t)((t) & 1) * FA_B;                             \
        uint32_t ob_ = (uint32_t)((t) & 1) * FB_B;                             \
        int k0_ = (t) << 6;                                                    \
        _Pragma("unroll")                                                      \
        for (int i_ = 0; i_ < 2; i_++)                                         \
            cpa16(aBase + oa_ + (uint32_t)aRowc[i_] * ROWB + (uint32_t)aChoff[i_] * 2, \
                  Ab + (size_t)aRowc[i_] * K + k0_ + aChoff[i_]);              \
        _Pragma("unroll")                                                      \
        for (int i_ = 0; i_ < 8; i_++)                                         \
            cpa16(bBase + ob_ + (uint32_t)bRowc[i_] * ROWB + (uint32_t)bChoff[i_] * 2, \
                  B + (size_t)bRowc[i_] * K + k0_ + bChoff[i_]);               \
        cpa_commit();                                                          \
    } while (0)

    FLOAD_TILE(0);

#pragma unroll 2
    for (int j = 0; j < NT; j++) {
        cpa_wait0();
        __syncthreads();
        if (j + 1 < NT) FLOAD_TILE(j + 1);

        uint32_t aOff = (uint32_t)(j & 1) * FA_B;
        uint32_t bOff = (uint32_t)(j & 1) * FB_B;
#pragma unroll
        for (int ks = 0; ks < 4; ks++) {
            uint32_t kb = (uint32_t)(ks * 32);
            uint32_t af[4][4], bf[4][2];
#pragma unroll
            for (int mi = 0; mi < 4; mi++)
                ldsm4(af[mi][0], af[mi][1], af[mi][2], af[mi][3],
                      aAddr + aOff + kb + (uint32_t)(mi * 16) * ROWB);
#pragma unroll
            for (int pi = 0; pi < 2; pi++)
                ldsm4(bf[2 * pi][0], bf[2 * pi][1], bf[2 * pi + 1][0], bf[2 * pi + 1][1],
                      bAddr + bOff + kb + (uint32_t)(pi * 16) * ROWB);
#pragma unroll
            for (int mi = 0; mi < 4; mi++)
#pragma unroll
                for (int ni = 0; ni < 4; ni++)
                    mma_bf16(acc[mi][ni], af[mi], bf[ni]);
        }
    }
    __syncthreads();

    float* stage = (float*)smem;
#pragma unroll
    for (int mi = 0; mi < 4; mi++) {
        int r0 = mi * 16 + grp;
#pragma unroll
        for (int ni = 0; ni < 4; ni++) {
            int c = wn + ni * 8 + tig * 2;
            float bv0 = __ldg(bias + c), bv1 = __ldg(bias + c + 1);
            stage[r0 * STG_S + c]           = acc[mi][ni][0] + bv0;
            stage[r0 * STG_S + c + 1]       = acc[mi][ni][1] + bv1;
            stage[(r0 + 8) * STG_S + c]     = acc[mi][ni][2] + bv0;
            stage[(r0 + 8) * STG_S + c + 1] = acc[mi][ni][3] + bv1;
        }
    }
    __syncthreads();

    float4 sv0 = *(const float4*)(lns + lane * 8);
    float4 sv1 = *(const float4*)(lns + lane * 8 + 4);
    float4 bv0 = *(const float4*)(lnb + lane * 8);
    float4 bv1 = *(const float4*)(lnb + lane * 8 + 4);
    float sc[8] = {sv0.x, sv0.y, sv0.z, sv0.w, sv1.x, sv1.y, sv1.z, sv1.w};
    float bi[8] = {bv0.x, bv0.y, bv0.z, bv0.w, bv1.x, bv1.y, bv1.z, bv1.w};

#pragma unroll
    for (int it = 0; it < 8; it++) {
        int tok = warp * 8 + it;
        size_t gbase = ((size_t)blockIdx.x * 64 + tok) * DMODEL + lane * 8;
        const float* sp = stage + tok * STG_S + lane * 8;

        float4 xv0 = *(const float4*)(x + gbase);
        float4 xv1 = *(const float4*)(x + gbase + 4);
        float v[8] = {xv0.x + sp[0], xv0.y + sp[1], xv0.z + sp[2], xv0.w + sp[3],
                      xv1.x + sp[4], xv1.y + sp[5], xv1.z + sp[6], xv1.w + sp[7]};

        float sum = 0.0f;
#pragma unroll
        for (int i = 0; i < 8; i++) sum += v[i];
#pragma unroll
        for (int o = 16; o > 0; o >>= 1) sum += __shfl_xor_sync(0xffffffffu, sum, o);
        float m = sum * (1.0f / 256.0f);

        float vs = 0.0f;
#pragma unroll
        for (int i = 0; i < 8; i++) { float d = v[i] - m; vs += d * d; }
#pragma unroll
        for (int o = 16; o > 0; o >>= 1) vs += __shfl_xor_sync(0xffffffffu, vs, o);
        float rstd = rsqrtf(vs * (1.0f / 256.0f) + 1e-5f);

        float o_[8];
#pragma unroll
        for (int i = 0; i < 8; i++) o_[i] = (v[i] - m) * rstd * sc[i] + bi[i];

        float4 w0 = {o_[0], o_[1], o_[2], o_[3]};
        float4 w1 = {o_[4], o_[5], o_[6], o_[7]};
        *(float4*)(x + gbase) = w0;
        *(float4*)(x + gbase + 4) = w1;
        if (wrXb) {
#pragma unroll
            for (int i = 0; i < 8; i += 2) {
                __nv_bfloat162 c2 = {__float2bfloat16_rn(o_[i]), __float2bfloat16_rn(o_[i + 1])};
                *(__nv_bfloat162*)(xb + gbase + i) = c2;
            }
        }
    }
}

// ---------------------------------------------------------------------------
// Tensor-core windowed attention (fp16 mma, fp32 softmax).
// ---------------------------------------------------------------------------
#define ATT_RS   40
#define ATT_MATH (64 * ATT_RS)
#define ATT_WARPH (2 * ATT_MATH)
#define ATT_SMEM (4 * ATT_WARPH * 2)

__global__ void __launch_bounds__(128, 4)
attn_tc(const __half* __restrict__ qkv, __nv_bfloat16* __restrict__ att)
{
    extern __shared__ __half ash[];
    int tid = threadIdx.x, warp = tid >> 5, lane = tid & 31;
    int w = blockIdx.x;
    int head = blockIdx.y * 4 + warp;
    int grp = lane >> 2, tig = lane & 3;

    __half* base = ash + warp * ATT_WARPH;
    uint32_t sb = (uint32_t)__cvta_generic_to_shared(base);

    const __half* src = qkv + (size_t)w * 64 * DQKV + head * 32;
#pragma unroll
    for (int m = 0; m < 2; m++) {
        const __half* ms = src + 256 + m * 256;
        __half* dst = base + m * ATT_MATH;
#pragma unroll
        for (int p = 0; p < 8; p++) {
            int c = p * 32 + lane;
            int row = c >> 2, ch = c & 3;
            *(uint4*)(dst + row * ATT_RS + ch * 8) =
                *(const uint4*)(ms + (size_t)row * DQKV + ch * 8);
        }
    }
    __syncwarp();

    const uint32_t Ks = sb;
    const uint32_t Vs = sb + ATT_MATH * 2;
    const __half* qbase = src;

    const float scale = 0.17677669529663687f;

#pragma unroll
    for (int qt = 0; qt < 4; qt++) {
        uint32_t qa[2][4];
#pragma unroll
        for (int ks = 0; ks < 2; ks++) {
            const __half* qp = qbase + (size_t)(qt * 16 + grp) * DQKV + ks * 16 + tig * 2;
            qa[ks][0] = *(const uint32_t*)(qp);
            qa[ks][1] = *(const uint32_t*)(qp + 8 * DQKV);
            qa[ks][2] = *(const uint32_t*)(qp + 8);
            qa[ks][3] = *(const uint32_t*)(qp + 8 * DQKV + 8);
        }

        float s[8][4];
#pragma unroll
        for (int nt2 = 0; nt2 < 8; nt2++)
#pragma unroll
            for (int r = 0; r < 4; r++) s[nt2][r] = 0.0f;

#pragma unroll
        for (int ks = 0; ks < 2; ks++) {
            uint32_t kf[8][2];
#pragma unroll
            for (int pi = 0; pi < 4; pi++) {
                uint32_t addr = Ks +
                    (uint32_t)((pi * 16 + (lane >> 4) * 8 + (lane & 7)) * ATT_RS +
                               ((lane >> 3) & 1) * 8 + ks * 16) * 2;
                ldsm4(kf[2 * pi][0], kf[2 * pi][1],
                      kf[2 * pi + 1][0], kf[2 * pi + 1][1], addr);
            }
#pragma unroll
            for (int nt2 = 0; nt2 < 8; nt2++)
                mma_fp16(s[nt2], qa[ks], kf[nt2]);
        }

        float mx0 = -1e30f, mx1 = -1e30f;
#pragma unroll
        for (int nt2 = 0; nt2 < 8; nt2++) {
            s[nt2][0] *= scale; s[nt2][1] *= scale;
            s[nt2][2] *= scale; s[nt2][3] *= scale;
            mx0 = fmaxf(mx0, fmaxf(s[nt2][0], s[nt2][1]));
            mx1 = fmaxf(mx1, fmaxf(s[nt2][2], s[nt2][3]));
        }
        mx0 = fmaxf(mx0, __shfl_xor_sync(0xffffffffu, mx0, 1));
        mx0 = fmaxf(mx0, __shfl_xor_sync(0xffffffffu, mx0, 2));
        mx1 = fmaxf(mx1, __shfl_xor_sync(0xffffffffu, mx1, 1));
        mx1 = fmaxf(mx1, __shfl_xor_sync(0xffffffffu, mx1, 2));

        float sm0 = 0.0f, sm1 = 0.0f;
#pragma unroll
        for (int nt2 = 0; nt2 < 8; nt2++) {
            s[nt2][0] = expf(s[nt2][0] - mx0);
            s[nt2][1] = expf(s[nt2][1] - mx0);
            s[nt2][2] = expf(s[nt2][2] - mx1);
            s[nt2][3] = expf(s[nt2][3] - mx1);
            sm0 += s[nt2][0] + s[nt2][1];
            sm1 += s[nt2][2] + s[nt2][3];
        }
        sm0 += __shfl_xor_sync(0xffffffffu, sm0, 1);
        sm0 += __shfl_xor_sync(0xffffffffu, sm0, 2);
        sm1 += __shfl_xor_sync(0xffffffffu, sm1, 1);
        sm1 += __shfl_xor_sync(0xffffffffu, sm1, 2);
        float inv0 = 1.0f / sm0, inv1 = 1.0f / sm1;

        uint32_t pa[4][4];
#pragma unroll
        for (int ks2 = 0; ks2 < 4; ks2++) {
            pa[ks2][0] = packh2(s[2 * ks2][0],     s[2 * ks2][1]);
            pa[ks2][1] = packh2(s[2 * ks2][2],     s[2 * ks2][3]);
            pa[ks2][2] = packh2(s[2 * ks2 + 1][0], s[2 * ks2 + 1][1]);
            pa[ks2][3] = packh2(s[2 * ks2 + 1][2], s[2 * ks2 + 1][3]);
        }

        float o[4][4];
#pragma unroll
        for (int nt2 = 0; nt2 < 4; nt2++)
#pragma unroll
            for (int r = 0; r < 4; r++) o[nt2][r] = 0.0f;

#pragma unroll
        for (int ks2 = 0; ks2 < 4; ks2++) {
            uint32_t vf[4][2];
#pragma unroll
            for (int np = 0; np < 2; np++) {
                uint32_t addr = Vs +
                    (uint32_t)((ks2 * 16 + ((lane >> 3) & 1) * 8 + (lane & 7)) * ATT_RS +
                               ((lane >> 4) + np * 2) * 8) * 2;
                ldsm4t(vf[2 * np][0], vf[2 * np][1],
                       vf[2 * np + 1][0], vf[2 * np + 1][1], addr);
            }
#pragma unroll
            for (int nt2 = 0; nt2 < 4; nt2++)
                mma_fp16(o[nt2], pa[ks2], vf[nt2]);
        }

        int row0 = w * 64 + qt * 16 + grp;
        __nv_bfloat16* ob = att + (size_t)row0 * DMODEL + head * 32 + tig * 2;
#pragma unroll
        for (int nt2 = 0; nt2 < 4; nt2++) {
            __nv_bfloat162 p0 = {__float2bfloat16_rn(o[nt2][0] * inv0),
                                 __float2bfloat16_rn(o[nt2][1] * inv0)};
            __nv_bfloat162 p1 = {__float2bfloat16_rn(o[nt2][2] * inv1),
                                 __float2bfloat16_rn(o[nt2][3] * inv1)};
            *(__nv_bfloat162*)(ob + nt2 * 8) = p0;
            *(__nv_bfloat162*)(ob + 8 * DMODEL + nt2 * 8) = p1;
        }
    }
}

// ---------------------------------------------------------------------------
// Final LN + transposed, fully-coalesced write to [B, C, H*W].
// ---------------------------------------------------------------------------
__global__ __launch_bounds__(256)
void final_ln_t(const float* __restrict__ x, const float* __restrict__ s,
                const float* __restrict__ b, float* __restrict__ out)
{
    __shared__ float stage[32][257];
    int bb = blockIdx.y, l0 = blockIdx.x * 32;
    int warp = threadIdx.x >> 5, lane = threadIdx.x & 31;

    float4 sv0 = *(const float4*)(s + lane * 8);
    float4 sv1 = *(const float4*)(s + lane * 8 + 4);
    float4 bv0 = *(const float4*)(b + lane * 8);
    float4 bv1 = *(const float4*)(b + lane * 8 + 4);
    float sc[8] = {sv0.x, sv0.y, sv0.z, sv0.w, sv1.x, sv1.y, sv1.z, sv1.w};
    float bi[8] = {bv0.x, bv0.y, bv0.z, bv0.w, bv1.x, bv1.y, bv1.z, bv1.w};

#pragma unroll
    for (int it = 0; it < 4; it++) {
        int tl = warp * 4 + it;
        size_t base = ((size_t)(bb * 1024 + l0 + tl)) * DMODEL + lane * 8;
        float4 v0 = *(const float4*)(x + base);
        float4 v1 = *(const float4*)(x + base + 4);
        float v[8] = {v0.x, v0.y, v0.z, v0.w, v1.x, v1.y, v1.z, v1.w};

        float sum = 0.0f;
#pragma unroll
        for (int i = 0; i < 8; i++) sum += v[i];
#pragma unroll
        for (int o = 16; o > 0; o >>= 1) sum += __shfl_xor_sync(0xffffffffu, sum, o);
        float m = sum * (1.0f / 256.0f);

        float vs = 0.0f;
#pragma unroll
        for (int i = 0; i < 8; i++) { float d = v[i] - m; vs += d * d; }
#pragma unroll
        for (int o = 16; o > 0; o >>= 1) vs += __shfl_xor_sync(0xffffffffu, vs, o);
        float rstd = rsqrtf(vs * (1.0f / 256.0f) + 1e-5f);

#pragma unroll
        for (int i = 0; i < 8; i++)
            stage[tl][lane * 8 + i] = (v[i] - m) * rstd * sc[i] + bi[i];
    }
    __syncthreads();

#pragma unroll
    for (int dd = warp; dd < DMODEL; dd += 8)
        out[((size_t)bb * DMODEL + dd) * 1024 + l0 + lane] = stage[lane][dd];
}

// ---------------------------------------------------------------------------
extern "C" void kernel_launch(void* const* d_in, const int* in_sizes, int n_in,
                              void* d_out, int out_size)
{
    const float* features = (const float*)d_in[0];
    const float* in_w  = (const float*)d_in[1];
    const float* in_b  = (const float*)d_in[2];
    const float* ow    = (const float*)d_in[3];
    const float* ob    = (const float*)d_in[4];
    const float* w1    = (const float*)d_in[5];
    const float* b1    = (const float*)d_in[6];
    const float* w2    = (const float*)d_in[7];
    const float* b2    = (const float*)d_in[8];
    const float* ln1s  = (const float*)d_in[9];
    const float* ln1b  = (const float*)d_in[10];
    const float* ln2s  = (const float*)d_in[11];
    const float* ln2b  = (const float*)d_in[12];
    const float* fns   = (const float*)d_in[13];
    const float* fnb   = (const float*)d_in[14];
    float* out = (float*)d_out;

    float* x;
    __half* qkvh;
    __nv_bfloat16 *xb, *att, *hh, *wb;
    cudaGetSymbolAddress((void**)&x,    g_x);
    cudaGetSymbolAddress((void**)&xb,   g_xb);
    cudaGetSymbolAddress((void**)&qkvh, g_qkv);
    cudaGetSymbolAddress((void**)&att,  g_att);
    cudaGetSymbolAddress((void**)&hh,   g_h);
    cudaGetSymbolAddress((void**)&wb,   g_wb);

    cudaFuncSetAttribute(gemm_bf16<4>, cudaFuncAttributeMaxDynamicSharedMemorySize, GSMEM_SZ);
    cudaFuncSetAttribute(gemm_ln<4>,   cudaFuncAttributeMaxDynamicSharedMemorySize, FG_SMEM);
    cudaFuncSetAttribute(gemm_ln<16>,  cudaFuncAttributeMaxDynamicSharedMemorySize, FG_SMEM);
    cudaFuncSetAttribute(attn_tc,      cudaFuncAttributeMaxDynamicSharedMemorySize, ATT_SMEM);

    cvt_all<<<(CV4 + 255) / 256, 256>>>(in_w, ow, w1, w2, wb);

    dim3 eb(32, 32);
    dim3 eg(32, 8, 32);
    embed_kernel<<<eg, eb>>>(features, x, xb);

    const int T = T_TOK;
    for (int i = 0; i < 3; i++) {
        gemm_bf16<4><<<dim3(DQKV / 128, T / 128), 256, GSMEM_SZ>>>(
            xb, wb + WT_INW + (size_t)i * DQKV * DMODEL, in_b + (size_t)i * DQKV,
            nullptr, qkvh, T, DQKV, 0, 2);
        attn_tc<<<dim3(512, 2), 128, ATT_SMEM>>>(qkvh, att);
        gemm_ln<4><<<T / 64, 256, FG_SMEM>>>(
            att, wb + WT_OW + (size_t)i * DMODEL * DMODEL, ob + (size_t)i * DMODEL,
            ln1s + (size_t)i * DMODEL, ln1b + (size_t)i * DMODEL, x, xb, 1);
        gemm_bf16<4><<<dim3(DFFN / 128, T / 128), 256, GSMEM_SZ>>>(
            xb, wb + WT_W1 + (size_t)i * DFFN * DMODEL, b1 + (size_t)i * DFFN,
            hh, nullptr, T, DFFN, 1, 1);
        gemm_ln<16><<<T / 64, 256, FG_SMEM>>>(
            hh, wb + WT_W2 + (size_t)i * DMODEL * DFFN, b2 + (size_t)i * DMODEL,
            ln2s + (size_t)i * DMODEL, ln2b + (size_t)i * DMODEL, x, xb,
            (i < 2) ? 1 : 0);
    }
    final_ln_t<<<dim3(32, 32), 256>>>(x, fns, fnb, out);
}

// round 16
// speedup vs baseline: 1.2068x; 1.0033x over previous
#include <cuda_runtime.h>
#include <cuda_bf16.h>
#include <cuda_fp16.h>
#include <math.h>
#include <stdint.h>

// ---------------------------------------------------------------------------
// EfficientTransformerEncoder: B=32, D=256 -> L=1024, NH=8, NL=3, DFF=1024,
// WIN=64. bf16 mma.sync GEMMs (3-stage cp.async, compile-time trip counts)
// + fp16 TC attention + fused LN epilogues.
// ---------------------------------------------------------------------------

#define T_TOK   32768
#define DMODEL  256
#define DQKV    768
#define DFFN    1024

__device__ float          g_x  [(size_t)T_TOK * DMODEL];
__device__ __nv_bfloat16  g_xb [(size_t)T_TOK * DMODEL];
__device__ __half         g_qkv[(size_t)T_TOK * DQKV];
__device__ __nv_bfloat16  g_att[(size_t)T_TOK * DMODEL];
__device__ __nv_bfloat16  g_h  [(size_t)T_TOK * DFFN];

#define WT_INW 0
#define WT_OW  (WT_INW + 3 * DQKV * DMODEL)
#define WT_W1  (WT_OW  + 3 * DMODEL * DMODEL)
#define WT_W2  (WT_W1  + 3 * DFFN * DMODEL)
#define WT_TOT (WT_W2  + 3 * DMODEL * DFFN)
__device__ __nv_bfloat16 g_wb[WT_TOT];

#define CV0 0
#define CV1 (WT_OW  / 4)
#define CV2 (WT_W1  / 4)
#define CV3 (WT_W2  / 4)
#define CV4 (WT_TOT / 4)

// ---------------------------------------------------------------------------
__global__ void cvt_all(const float* __restrict__ s0, const float* __restrict__ s1,
                        const float* __restrict__ s2, const float* __restrict__ s3,
                        __nv_bfloat16* __restrict__ dst) {
    int i = blockIdx.x * blockDim.x + threadIdx.x;
    if (i >= CV4) return;
    const float* src;
    int off;
    if (i < CV1)      { src = s0; off = i - CV0; }
    else if (i < CV2) { src = s1; off = i - CV1; }
    else if (i < CV3) { src = s2; off = i - CV2; }
    else              { src = s3; off = i - CV3; }
    float4 v = ((const float4*)src)[off];
    __nv_bfloat162 lo = {__float2bfloat16_rn(v.x), __float2bfloat16_rn(v.y)};
    __nv_bfloat162 hi = {__float2bfloat16_rn(v.z), __float2bfloat16_rn(v.w)};
    ((__nv_bfloat162*)dst)[i * 2]     = lo;
    ((__nv_bfloat162*)dst)[i * 2 + 1] = hi;
}

// ---------------------------------------------------------------------------
// Embed: x[b,l,d] = features[b,d,l] + PE(l,d).  Frequencies hoisted to smem
// (16 expf per block instead of 1024; sin/cos per element unchanged).
// ---------------------------------------------------------------------------
__global__ void embed_kernel(const float* __restrict__ f,
                             float* __restrict__ x, __nv_bfloat16* __restrict__ xb) {
    __shared__ float tile[32][33];
    __shared__ float freq[16];
    int b  = blockIdx.z;
    int l0 = blockIdx.x * 32, d0 = blockIdx.y * 32;
    int tx = threadIdx.x, ty = threadIdx.y;

    if (ty == 0 && tx < 16) {
        int i = (d0 >> 1) + tx;   // pair index for d = d0 + 2*tx
        freq[tx] = expf(-(float)(2 * i) * 0.0359778920439f);  // ln(10000)/256
    }
    tile[ty][tx] = f[((size_t)b * DMODEL + d0 + ty) * 1024 + l0 + tx];
    __syncthreads();

    int l = l0 + ty, d = d0 + tx;
    float ang = (float)l * freq[tx >> 1];
    float pe  = (d & 1) ? cosf(ang) : sinf(ang);
    float v = tile[tx][ty] + pe;
    size_t idx = ((size_t)b * 1024 + l) * DMODEL + d;
    x[idx]  = v;
    xb[idx] = __float2bfloat16_rn(v);
}

// ---------------------------------------------------------------------------
__device__ __forceinline__ float gelu_exact(float v) {
    return 0.5f * v * (1.0f + erff(v * 0.7071067811865476f));
}

__device__ __forceinline__ void mma_bf16(float c[4], const uint32_t a[4], const uint32_t b[2]) {
    asm volatile(
        "mma.sync.aligned.m16n8k16.row.col.f32.bf16.bf16.f32 "
        "{%0,%1,%2,%3}, {%4,%5,%6,%7}, {%8,%9}, {%0,%1,%2,%3};\n"
        : "+f"(c[0]), "+f"(c[1]), "+f"(c[2]), "+f"(c[3])
        : "r"(a[0]), "r"(a[1]), "r"(a[2]), "r"(a[3]), "r"(b[0]), "r"(b[1]));
}

__device__ __forceinline__ void mma_fp16(float c[4], const uint32_t a[4], const uint32_t b[2]) {
    asm volatile(
        "mma.sync.aligned.m16n8k16.row.col.f32.f16.f16.f32 "
        "{%0,%1,%2,%3}, {%4,%5,%6,%7}, {%8,%9}, {%0,%1,%2,%3};\n"
        : "+f"(c[0]), "+f"(c[1]), "+f"(c[2]), "+f"(c[3])
        : "r"(a[0]), "r"(a[1]), "r"(a[2]), "r"(a[3]), "r"(b[0]), "r"(b[1]));
}

__device__ __forceinline__ void ldsm4(uint32_t& r0, uint32_t& r1, uint32_t& r2, uint32_t& r3,
                                      uint32_t addr) {
    asm volatile("ldmatrix.sync.aligned.m8n8.x4.shared.b16 {%0,%1,%2,%3}, [%4];"
                 : "=r"(r0), "=r"(r1), "=r"(r2), "=r"(r3) : "r"(addr));
}
__device__ __forceinline__ void ldsm4t(uint32_t& r0, uint32_t& r1, uint32_t& r2, uint32_t& r3,
                                       uint32_t addr) {
    asm volatile("ldmatrix.sync.aligned.m8n8.x4.trans.shared.b16 {%0,%1,%2,%3}, [%4];"
                 : "=r"(r0), "=r"(r1), "=r"(r2), "=r"(r3) : "r"(addr));
}

__device__ __forceinline__ void cpa16(uint32_t dst, const void* src) {
    asm volatile("cp.async.cg.shared.global [%0], [%1], 16;\n" :: "r"(dst), "l"(src));
}
__device__ __forceinline__ void cpa_commit() {
    asm volatile("cp.async.commit_group;\n" ::: "memory");
}
__device__ __forceinline__ void cpa_wait0() {
    asm volatile("cp.async.wait_group 0;\n" ::: "memory");
}
__device__ __forceinline__ void cpa_wait1() {
    asm volatile("cp.async.wait_group 1;\n" ::: "memory");
}

__device__ __forceinline__ uint32_t packh2(float x, float y) {
    __half2 h = __floats2half2_rn(x, y);
    return *reinterpret_cast<uint32_t*>(&h);
}

#define SMH  72
#define ROWB (SMH * 2)

// ---------------------------------------------------------------------------
// 128x128 bf16 GEMM, 3-stage cp.async pipeline, compile-time NT tiles (K=NT*64).
// outmode: 1 -> bf16 Cb, 2 -> fp16 Ch.
// ---------------------------------------------------------------------------
#define MATB (128 * ROWB)
#define GSMEM_SZ (6 * MATB)

template<int NT>
__global__ void __launch_bounds__(256, 2)
gemm_bf16(const __nv_bfloat16* __restrict__ A, const __nv_bfloat16* __restrict__ B,
          const float* __restrict__ bias,
          __nv_bfloat16* __restrict__ Cb, __half* __restrict__ Ch,
          int M, int N, int act, int outmode)
{
    constexpr int K = NT * 64;
    extern __shared__ __nv_bfloat16 smem[];
    uint32_t sbase = (uint32_t)__cvta_generic_to_shared(smem);
    uint32_t aBase = sbase;
    uint32_t bBase = sbase + 3 * MATB;

    int tid  = threadIdx.x;
    int warp = tid >> 5, lane = tid & 31;
    int wm = (warp >> 2) * 64;
    int wn = (warp & 3) * 32;
    int grp = lane >> 2, tig = lane & 3;

    const __nv_bfloat16* Ab = A + (size_t)blockIdx.y * 128 * K;
    const __nv_bfloat16* Bb = B + (size_t)blockIdx.x * 128 * K;

    int rowc[4], choff[4];
#pragma unroll
    for (int i = 0; i < 4; i++) {
        int c = tid + 256 * i;
        rowc[i]  = c >> 3;
        choff[i] = (c & 7) * 8;
    }

    int aRow = wm + ((lane >> 3) & 1) * 8 + (lane & 7);
    int aK   = (lane >> 4) * 8;
    int bRow = wn + (lane >> 4) * 8 + (lane & 7);
    int bK   = ((lane >> 3) & 1) * 8;
    uint32_t aAddr = aBase + (uint32_t)aRow * ROWB + (uint32_t)aK * 2;
    uint32_t bAddr = bBase + (uint32_t)bRow * ROWB + (uint32_t)bK * 2;

    float acc[4][4][4];
#pragma unroll
    for (int mi = 0; mi < 4; mi++)
#pragma unroll
        for (int ni = 0; ni < 4; ni++)
#pragma unroll
            for (int r = 0; r < 4; r++) acc[mi][ni][r] = 0.0f;

#define LOAD_TILE(t)                                                           \
    do {                                                                       \
        uint32_t off_ = (uint32_t)((t) % 3) * MATB;                            \
        int k0_ = (t) << 6;                                                    \
        _Pragma("unroll")                                                      \
        for (int i_ = 0; i_ < 4; i_++) {                                       \
            uint32_t d_ = off_ + (uint32_t)rowc[i_] * ROWB + (uint32_t)choff[i_] * 2; \
            cpa16(aBase + d_, Ab + (size_t)rowc[i_] * K + k0_ + choff[i_]);    \
            cpa16(bBase + d_, Bb + (size_t)rowc[i_] * K + k0_ + choff[i_]);    \
        }                                                                      \
        cpa_commit();                                                          \
    } while (0)

    LOAD_TILE(0);
    if (NT > 1) LOAD_TILE(1);

#pragma unroll
    for (int j = 0; j < NT; j++) {
        if (j + 1 < NT) cpa_wait1(); else cpa_wait0();
        __syncthreads();
        if (j + 2 < NT) LOAD_TILE(j + 2);

        uint32_t bufOff = (uint32_t)(j % 3) * MATB;
#pragma unroll
        for (int ks = 0; ks < 4; ks++) {
            uint32_t kOff = bufOff + (uint32_t)(ks * 32);
            uint32_t af[4][4], bf[4][2];
#pragma unroll
            for (int mi = 0; mi < 4; mi++)
                ldsm4(af[mi][0], af[mi][1], af[mi][2], af[mi][3],
                      aAddr + kOff + (uint32_t)(mi * 16) * ROWB);
#pragma unroll
            for (int pi = 0; pi < 2; pi++)
                ldsm4(bf[2 * pi][0], bf[2 * pi][1], bf[2 * pi + 1][0], bf[2 * pi + 1][1],
                      bAddr + kOff + (uint32_t)(pi * 16) * ROWB);
#pragma unroll
            for (int mi = 0; mi < 4; mi++)
#pragma unroll
                for (int ni = 0; ni < 4; ni++)
                    mma_bf16(acc[mi][ni], af[mi], bf[ni]);
        }
    }

#pragma unroll
    for (int mi = 0; mi < 4; mi++) {
        int r0 = blockIdx.y * 128 + wm + mi * 16 + grp;
#pragma unroll
        for (int ni = 0; ni < 4; ni++) {
            int c = blockIdx.x * 128 + wn + ni * 8 + tig * 2;
            float bv0 = __ldg(bias + c), bv1 = __ldg(bias + c + 1);
            float v0 = acc[mi][ni][0] + bv0;
            float v1 = acc[mi][ni][1] + bv1;
            float v2 = acc[mi][ni][2] + bv0;
            float v3 = acc[mi][ni][3] + bv1;
            if (act == 1) {
                v0 = gelu_exact(v0); v1 = gelu_exact(v1);
                v2 = gelu_exact(v2); v3 = gelu_exact(v3);
            }
            if (outmode == 1) {
                __nv_bfloat162 p0 = {__float2bfloat16_rn(v0), __float2bfloat16_rn(v1)};
                __nv_bfloat162 p1 = {__float2bfloat16_rn(v2), __float2bfloat16_rn(v3)};
                *(__nv_bfloat162*)(Cb + (size_t)r0 * N + c) = p0;
                *(__nv_bfloat162*)(Cb + (size_t)(r0 + 8) * N + c) = p1;
            } else {
                uint32_t p0 = packh2(v0, v1), p1 = packh2(v2, v3);
                *(uint32_t*)(Ch + (size_t)r0 * N + c) = p0;
                *(uint32_t*)(Ch + (size_t)(r0 + 8) * N + c) = p1;
            }
        }
    }
}

// ---------------------------------------------------------------------------
// Fused GEMM(N=256) + residual + LayerNorm. Block tile 64x256, 8 warps (1x8).
// Compile-time NT tiles (K=NT*64). wrXb: 0 -> skip bf16 xb write.
// ---------------------------------------------------------------------------
#define FA_B  (64 * ROWB)
#define FB_B  (256 * ROWB)
#define FG_SMEM (2 * FA_B + 2 * FB_B)
#define STG_S 264

template<int NT>
__global__ void __launch_bounds__(256, 2)
gemm_ln(const __nv_bfloat16* __restrict__ A, const __nv_bfloat16* __restrict__ B,
        const float* __restrict__ bias,
        const float* __restrict__ lns, const float* __restrict__ lnb,
        float* __restrict__ x, __nv_bfloat16* __restrict__ xb, int wrXb)
{
    constexpr int K = NT * 64;
    extern __shared__ __nv_bfloat16 smem[];
    uint32_t sbase = (uint32_t)__cvta_generic_to_shared(smem);
    uint32_t aBase = sbase;
    uint32_t bBase = sbase + 2 * FA_B;

    int tid  = threadIdx.x;
    int warp = tid >> 5, lane = tid & 31;
    int wn = warp * 32;
    int grp = lane >> 2, tig = lane & 3;

    const __nv_bfloat16* Ab = A + (size_t)blockIdx.x * 64 * K;

    int aRowc[2], aChoff[2];
#pragma unroll
    for (int i = 0; i < 2; i++) {
        int c = tid + 256 * i;
        aRowc[i]  = c >> 3;
        aChoff[i] = (c & 7) * 8;
    }
    int bRowc[8], bChoff[8];
#pragma unroll
    for (int i = 0; i < 8; i++) {
        int c = tid + 256 * i;
        bRowc[i]  = c >> 3;
        bChoff[i] = (c & 7) * 8;
    }

    int aRow = ((lane >> 3) & 1) * 8 + (lane & 7);
    int aK   = (lane >> 4) * 8;
    int bRow = wn + (lane >> 4) * 8 + (lane & 7);
    int bK   = ((lane >> 3) & 1) * 8;
    uint32_t aAddr = aBase + (uint32_t)aRow * ROWB + (uint32_t)aK * 2;
    uint32_t bAddr = bBase + (uint32_t)bRow * ROWB + (uint32_t)bK * 2;

    float acc[4][4][4];
#pragma unroll
    for (int mi = 0; mi < 4; mi++)
#pragma unroll
        for (int ni = 0; ni < 4; ni++)
#pragma unroll
            for (int r = 0; r < 4; r++) acc[mi][ni][r] = 0.0f;

#define FLOAD_TILE(t)                                                          \
    do {                                                                       \
        uint32_t oa_ = (uint32_t)((t) & 1) * FA_B;                             \
        uint32_t ob_ = (uint32_t)((t) & 1) * FB_B;                             \
        int k0_ = (t) << 6;                                                    \
        _Pragma("unroll")                                                      \
        for (int i_ = 0; i_ < 2; i_++)                                         \
            cpa16(aBase + oa_ + (uint32_t)aRowc[i_] * ROWB + (uint32_t)aChoff[i_] * 2, \
                  Ab + (size_t)aRowc[i_] * K + k0_ + aChoff[i_]);              \
        _Pragma("unroll")                                                      \
        for (int i_ = 0; i_ < 8; i_++)                                         \
            cpa16(bBase + ob_ + (uint32_t)bRowc[i_] * ROWB + (uint32_t)bChoff[i_] * 2, \
                  B + (size_t)bRowc[i_] * K + k0_ + bChoff[i_]);               \
        cpa_commit();                                                          \
    } while (0)

    FLOAD_TILE(0);

#pragma unroll 4
    for (int j = 0; j < NT; j++) {
        cpa_wait0();
        __syncthreads();
        if (j + 1 < NT) FLOAD_TILE(j + 1);

        uint32_t aOff = (uint32_t)(j & 1) * FA_B;
        uint32_t bOff = (uint32_t)(j & 1) * FB_B;
#pragma unroll
        for (int ks = 0; ks < 4; ks++) {
            uint32_t kb = (uint32_t)(ks * 32);
            uint32_t af[4][4], bf[4][2];
#pragma unroll
            for (int mi = 0; mi < 4; mi++)
                ldsm4(af[mi][0], af[mi][1], af[mi][2], af[mi][3],
                      aAddr + aOff + kb + (uint32_t)(mi * 16) * ROWB);
#pragma unroll
            for (int pi = 0; pi < 2; pi++)
                ldsm4(bf[2 * pi][0], bf[2 * pi][1], bf[2 * pi + 1][0], bf[2 * pi + 1][1],
                      bAddr + bOff + kb + (uint32_t)(pi * 16) * ROWB);
#pragma unroll
            for (int mi = 0; mi < 4; mi++)
#pragma unroll
                for (int ni = 0; ni < 4; ni++)
                    mma_bf16(acc[mi][ni], af[mi], bf[ni]);
        }
    }
    __syncthreads();

    float* stage = (float*)smem;
#pragma unroll
    for (int mi = 0; mi < 4; mi++) {
        int r0 = mi * 16 + grp;
#pragma unroll
        for (int ni = 0; ni < 4; ni++) {
            int c = wn + ni * 8 + tig * 2;
            float bv0 = __ldg(bias + c), bv1 = __ldg(bias + c + 1);
            stage[r0 * STG_S + c]           = acc[mi][ni][0] + bv0;
            stage[r0 * STG_S + c + 1]       = acc[mi][ni][1] + bv1;
            stage[(r0 + 8) * STG_S + c]     = acc[mi][ni][2] + bv0;
            stage[(r0 + 8) * STG_S + c + 1] = acc[mi][ni][3] + bv1;
        }
    }
    __syncthreads();

    float4 sv0 = *(const float4*)(lns + lane * 8);
    float4 sv1 = *(const float4*)(lns + lane * 8 + 4);
    float4 bv0 = *(const float4*)(lnb + lane * 8);
    float4 bv1 = *(const float4*)(lnb + lane * 8 + 4);
    float sc[8] = {sv0.x, sv0.y, sv0.z, sv0.w, sv1.x, sv1.y, sv1.z, sv1.w};
    float bi[8] = {bv0.x, bv0.y, bv0.z, bv0.w, bv1.x, bv1.y, bv1.z, bv1.w};

#pragma unroll
    for (int it = 0; it < 8; it++) {
        int tok = warp * 8 + it;
        size_t gbase = ((size_t)blockIdx.x * 64 + tok) * DMODEL + lane * 8;
        const float* sp = stage + tok * STG_S + lane * 8;

        float4 xv0 = *(const float4*)(x + gbase);
        float4 xv1 = *(const float4*)(x + gbase + 4);
        float v[8] = {xv0.x + sp[0], xv0.y + sp[1], xv0.z + sp[2], xv0.w + sp[3],
                      xv1.x + sp[4], xv1.y + sp[5], xv1.z + sp[6], xv1.w + sp[7]};

        float sum = 0.0f;
#pragma unroll
        for (int i = 0; i < 8; i++) sum += v[i];
#pragma unroll
        for (int o = 16; o > 0; o >>= 1) sum += __shfl_xor_sync(0xffffffffu, sum, o);
        float m = sum * (1.0f / 256.0f);

        float vs = 0.0f;
#pragma unroll
        for (int i = 0; i < 8; i++) { float d = v[i] - m; vs += d * d; }
#pragma unroll
        for (int o = 16; o > 0; o >>= 1) vs += __shfl_xor_sync(0xffffffffu, vs, o);
        float rstd = rsqrtf(vs * (1.0f / 256.0f) + 1e-5f);

        float o_[8];
#pragma unroll
        for (int i = 0; i < 8; i++) o_[i] = (v[i] - m) * rstd * sc[i] + bi[i];

        float4 w0 = {o_[0], o_[1], o_[2], o_[3]};
        float4 w1 = {o_[4], o_[5], o_[6], o_[7]};
        *(float4*)(x + gbase) = w0;
        *(float4*)(x + gbase + 4) = w1;
        if (wrXb) {
#pragma unroll
            for (int i = 0; i < 8; i += 2) {
                __nv_bfloat162 c2 = {__float2bfloat16_rn(o_[i]), __float2bfloat16_rn(o_[i + 1])};
                *(__nv_bfloat162*)(xb + gbase + i) = c2;
            }
        }
    }
}

// ---------------------------------------------------------------------------
// Tensor-core windowed attention (fp16 mma, fp32 softmax).
// ---------------------------------------------------------------------------
#define ATT_RS   40
#define ATT_MATH (64 * ATT_RS)
#define ATT_WARPH (2 * ATT_MATH)
#define ATT_SMEM (4 * ATT_WARPH * 2)

__global__ void __launch_bounds__(128, 4)
attn_tc(const __half* __restrict__ qkv, __nv_bfloat16* __restrict__ att)
{
    extern __shared__ __half ash[];
    int tid = threadIdx.x, warp = tid >> 5, lane = tid & 31;
    int w = blockIdx.x;
    int head = blockIdx.y * 4 + warp;
    int grp = lane >> 2, tig = lane & 3;

    __half* base = ash + warp * ATT_WARPH;
    uint32_t sb = (uint32_t)__cvta_generic_to_shared(base);

    const __half* src = qkv + (size_t)w * 64 * DQKV + head * 32;
#pragma unroll
    for (int m = 0; m < 2; m++) {
        const __half* ms = src + 256 + m * 256;
        __half* dst = base + m * ATT_MATH;
#pragma unroll
        for (int p = 0; p < 8; p++) {
            int c = p * 32 + lane;
            int row = c >> 2, ch = c & 3;
            *(uint4*)(dst + row * ATT_RS + ch * 8) =
                *(const uint4*)(ms + (size_t)row * DQKV + ch * 8);
        }
    }
    __syncwarp();

    const uint32_t Ks = sb;
    const uint32_t Vs = sb + ATT_MATH * 2;
    const __half* qbase = src;

    const float scale = 0.17677669529663687f;

#pragma unroll
    for (int qt = 0; qt < 4; qt++) {
        uint32_t qa[2][4];
#pragma unroll
        for (int ks = 0; ks < 2; ks++) {
            const __half* qp = qbase + (size_t)(qt * 16 + grp) * DQKV + ks * 16 + tig * 2;
            qa[ks][0] = *(const uint32_t*)(qp);
            qa[ks][1] = *(const uint32_t*)(qp + 8 * DQKV);
            qa[ks][2] = *(const uint32_t*)(qp + 8);
            qa[ks][3] = *(const uint32_t*)(qp + 8 * DQKV + 8);
        }

        float s[8][4];
#pragma unroll
        for (int nt2 = 0; nt2 < 8; nt2++)
#pragma unroll
            for (int r = 0; r < 4; r++) s[nt2][r] = 0.0f;

#pragma unroll
        for (int ks = 0; ks < 2; ks++) {
            uint32_t kf[8][2];
#pragma unroll
            for (int pi = 0; pi < 4; pi++) {
                uint32_t addr = Ks +
                    (uint32_t)((pi * 16 + (lane >> 4) * 8 + (lane & 7)) * ATT_RS +
                               ((lane >> 3) & 1) * 8 + ks * 16) * 2;
                ldsm4(kf[2 * pi][0], kf[2 * pi][1],
                      kf[2 * pi + 1][0], kf[2 * pi + 1][1], addr);
            }
#pragma unroll
            for (int nt2 = 0; nt2 < 8; nt2++)
                mma_fp16(s[nt2], qa[ks], kf[nt2]);
        }

        float mx0 = -1e30f, mx1 = -1e30f;
#pragma unroll
        for (int nt2 = 0; nt2 < 8; nt2++) {
            s[nt2][0] *= scale; s[nt2][1] *= scale;
            s[nt2][2] *= scale; s[nt2][3] *= scale;
            mx0 = fmaxf(mx0, fmaxf(s[nt2][0], s[nt2][1]));
            mx1 = fmaxf(mx1, fmaxf(s[nt2][2], s[nt2][3]));
        }
        mx0 = fmaxf(mx0, __shfl_xor_sync(0xffffffffu, mx0, 1));
        mx0 = fmaxf(mx0, __shfl_xor_sync(0xffffffffu, mx0, 2));
        mx1 = fmaxf(mx1, __shfl_xor_sync(0xffffffffu, mx1, 1));
        mx1 = fmaxf(mx1, __shfl_xor_sync(0xffffffffu, mx1, 2));

        float sm0 = 0.0f, sm1 = 0.0f;
#pragma unroll
        for (int nt2 = 0; nt2 < 8; nt2++) {
            s[nt2][0] = expf(s[nt2][0] - mx0);
            s[nt2][1] = expf(s[nt2][1] - mx0);
            s[nt2][2] = expf(s[nt2][2] - mx1);
            s[nt2][3] = expf(s[nt2][3] - mx1);
            sm0 += s[nt2][0] + s[nt2][1];
            sm1 += s[nt2][2] + s[nt2][3];
        }
        sm0 += __shfl_xor_sync(0xffffffffu, sm0, 1);
        sm0 += __shfl_xor_sync(0xffffffffu, sm0, 2);
        sm1 += __shfl_xor_sync(0xffffffffu, sm1, 1);
        sm1 += __shfl_xor_sync(0xffffffffu, sm1, 2);
        float inv0 = 1.0f / sm0, inv1 = 1.0f / sm1;

        uint32_t pa[4][4];
#pragma unroll
        for (int ks2 = 0; ks2 < 4; ks2++) {
            pa[ks2][0] = packh2(s[2 * ks2][0],     s[2 * ks2][1]);
            pa[ks2][1] = packh2(s[2 * ks2][2],     s[2 * ks2][3]);
            pa[ks2][2] = packh2(s[2 * ks2 + 1][0], s[2 * ks2 + 1][1]);
            pa[ks2][3] = packh2(s[2 * ks2 + 1][2], s[2 * ks2 + 1][3]);
        }

        float o[4][4];
#pragma unroll
        for (int nt2 = 0; nt2 < 4; nt2++)
#pragma unroll
            for (int r = 0; r < 4; r++) o[nt2][r] = 0.0f;

#pragma unroll
        for (int ks2 = 0; ks2 < 4; ks2++) {
            uint32_t vf[4][2];
#pragma unroll
            for (int np = 0; np < 2; np++) {
                uint32_t addr = Vs +
                    (uint32_t)((ks2 * 16 + ((lane >> 3) & 1) * 8 + (lane & 7)) * ATT_RS +
                               ((lane >> 4) + np * 2) * 8) * 2;
                ldsm4t(vf[2 * np][0], vf[2 * np][1],
                       vf[2 * np + 1][0], vf[2 * np + 1][1], addr);
            }
#pragma unroll
            for (int nt2 = 0; nt2 < 4; nt2++)
                mma_fp16(o[nt2], pa[ks2], vf[nt2]);
        }

        int row0 = w * 64 + qt * 16 + grp;
        __nv_bfloat16* ob = att + (size_t)row0 * DMODEL + head * 32 + tig * 2;
#pragma unroll
        for (int nt2 = 0; nt2 < 4; nt2++) {
            __nv_bfloat162 p0 = {__float2bfloat16_rn(o[nt2][0] * inv0),
                                 __float2bfloat16_rn(o[nt2][1] * inv0)};
            __nv_bfloat162 p1 = {__float2bfloat16_rn(o[nt2][2] * inv1),
                                 __float2bfloat16_rn(o[nt2][3] * inv1)};
            *(__nv_bfloat162*)(ob + nt2 * 8) = p0;
            *(__nv_bfloat162*)(ob + 8 * DMODEL + nt2 * 8) = p1;
        }
    }
}

// ---------------------------------------------------------------------------
// Final LN + transposed, fully-coalesced write to [B, C, H*W].
// ---------------------------------------------------------------------------
__global__ __launch_bounds__(256)
void final_ln_t(const float* __restrict__ x, const float* __restrict__ s,
                const float* __restrict__ b, float* __restrict__ out)
{
    __shared__ float stage[32][257];
    int bb = blockIdx.y, l0 = blockIdx.x * 32;
    int warp = threadIdx.x >> 5, lane = threadIdx.x & 31;

    float4 sv0 = *(const float4*)(s + lane * 8);
    float4 sv1 = *(const float4*)(s + lane * 8 + 4);
    float4 bv0 = *(const float4*)(b + lane * 8);
    float4 bv1 = *(const float4*)(b + lane * 8 + 4);
    float sc[8] = {sv0.x, sv0.y, sv0.z, sv0.w, sv1.x, sv1.y, sv1.z, sv1.w};
    float bi[8] = {bv0.x, bv0.y, bv0.z, bv0.w, bv1.x, bv1.y, bv1.z, bv1.w};

#pragma unroll
    for (int it = 0; it < 4; it++) {
        int tl = warp * 4 + it;
        size_t base = ((size_t)(bb * 1024 + l0 + tl)) * DMODEL + lane * 8;
        float4 v0 = *(const float4*)(x + base);
        float4 v1 = *(const float4*)(x + base + 4);
        float v[8] = {v0.x, v0.y, v0.z, v0.w, v1.x, v1.y, v1.z, v1.w};

        float sum = 0.0f;
#pragma unroll
        for (int i = 0; i < 8; i++) sum += v[i];
#pragma unroll
        for (int o = 16; o > 0; o >>= 1) sum += __shfl_xor_sync(0xffffffffu, sum, o);
        float m = sum * (1.0f / 256.0f);

        float vs = 0.0f;
#pragma unroll
        for (int i = 0; i < 8; i++) { float d = v[i] - m; vs += d * d; }
#pragma unroll
        for (int o = 16; o > 0; o >>= 1) vs += __shfl_xor_sync(0xffffffffu, vs, o);
        float rstd = rsqrtf(vs * (1.0f / 256.0f) + 1e-5f);

#pragma unroll
        for (int i = 0; i < 8; i++)
            stage[tl][lane * 8 + i] = (v[i] - m) * rstd * sc[i] + bi[i];
    }
    __syncthreads();

#pragma unroll
    for (int dd = warp; dd < DMODEL; dd += 8)
        out[((size_t)bb * DMODEL + dd) * 1024 + l0 + lane] = stage[lane][dd];
}

// ---------------------------------------------------------------------------
extern "C" void kernel_launch(void* const* d_in, const int* in_sizes, int n_in,
                              void* d_out, int out_size)
{
    const float* features = (const float*)d_in[0];
    const float* in_w  = (const float*)d_in[1];
    const float* in_b  = (const float*)d_in[2];
    const float* ow    = (const float*)d_in[3];
    const float* ob    = (const float*)d_in[4];
    const float* w1    = (const float*)d_in[5];
    const float* b1    = (const float*)d_in[6];
    const float* w2    = (const float*)d_in[7];
    const float* b2    = (const float*)d_in[8];
    const float* ln1s  = (const float*)d_in[9];
    const float* ln1b  = (const float*)d_in[10];
    const float* ln2s  = (const float*)d_in[11];
    const float* ln2b  = (const float*)d_in[12];
    const float* fns   = (const float*)d_in[13];
    const float* fnb   = (const float*)d_in[14];
    float* out = (float*)d_out;

    float* x;
    __half* qkvh;
    __nv_bfloat16 *xb, *att, *hh, *wb;
    cudaGetSymbolAddress((void**)&x,    g_x);
    cudaGetSymbolAddress((void**)&xb,   g_xb);
    cudaGetSymbolAddress((void**)&qkvh, g_qkv);
    cudaGetSymbolAddress((void**)&att,  g_att);
    cudaGetSymbolAddress((void**)&hh,   g_h);
    cudaGetSymbolAddress((void**)&wb,   g_wb);

    cudaFuncSetAttribute(gemm_bf16<4>, cudaFuncAttributeMaxDynamicSharedMemorySize, GSMEM_SZ);
    cudaFuncSetAttribute(gemm_ln<4>,   cudaFuncAttributeMaxDynamicSharedMemorySize, FG_SMEM);
    cudaFuncSetAttribute(gemm_ln<16>,  cudaFuncAttributeMaxDynamicSharedMemorySize, FG_SMEM);
    cudaFuncSetAttribute(attn_tc,      cudaFuncAttributeMaxDynamicSharedMemorySize, ATT_SMEM);

    cvt_all<<<(CV4 + 255) / 256, 256>>>(in_w, ow, w1, w2, wb);

    dim3 eb(32, 32);
    dim3 eg(32, 8, 32);
    embed_kernel<<<eg, eb>>>(features, x, xb);

    const int T = T_TOK;
    for (int i = 0; i < 3; i++) {
        gemm_bf16<4><<<dim3(DQKV / 128, T / 128), 256, GSMEM_SZ>>>(
            xb, wb + WT_INW + (size_t)i * DQKV * DMODEL, in_b + (size_t)i * DQKV,
            nullptr, qkvh, T, DQKV, 0, 2);
        attn_tc<<<dim3(512, 2), 128, ATT_SMEM>>>(qkvh, att);
        gemm_ln<4><<<T / 64, 256, FG_SMEM>>>(
            att, wb + WT_OW + (size_t)i * DMODEL * DMODEL, ob + (size_t)i * DMODEL,
            ln1s + (size_t)i * DMODEL, ln1b + (size_t)i * DMODEL, x, xb, 1);
        gemm_bf16<4><<<dim3(DFFN / 128, T / 128), 256, GSMEM_SZ>>>(
            xb, wb + WT_W1 + (size_t)i * DFFN * DMODEL, b1 + (size_t)i * DFFN,
            hh, nullptr, T, DFFN, 1, 1);
        gemm_ln<16><<<T / 64, 256, FG_SMEM>>>(
            hh, wb + WT_W2 + (size_t)i * DMODEL * DFFN, b2 + (size_t)i * DMODEL,
            ln2s + (size_t)i * DMODEL, ln2b + (size_t)i * DMODEL, x, xb,
            (i < 2) ? 1 : 0);
    }
    final_ln_t<<<dim3(32, 32), 256>>>(x, fns, fnb, out);
}